// round 10
// baseline (speedup 1.0000x reference)
#include <cuda_runtime.h>
#include <math.h>

#define Bq 4
#define Qn 1024
#define Tn 1024
#define Hn 16
#define Mn 1024
#define Kd 64
#define Vd 64

typedef unsigned long long u64;

// ---------------- scratch (static device globals; no runtime alloc) ----------
__device__ float g_q[Bq*Hn*Qn*Kd];     // query * kscale  [b][h][q][d]
__device__ float g_k[Bq*Hn*Tn*Kd];     // key             [b][h][t][d]
__device__ float g_v[Bq*Hn*Tn*Vd];     // value           [b][h][t][d]
__device__ float g_preF[Bq*Qn*Hn*Vd];  // att @ V flat    [b*1024+q][h*64+d]
__device__ float g_m[Bq*Hn*Qn];
__device__ float g_l[Bq*Hn*Qn];
__device__ float g_rowocc[Bq*Qn];
__device__ float g_colact[Bq*Tn];
__device__ float g_colsum[Bq*Tn];

// ---------------- f32x2 helpers ----------------------------------------------
__device__ __forceinline__ u64 dup2(float v) {
    u64 d; asm("mov.b64 %0, {%1, %1};" : "=l"(d) : "r"(__float_as_uint(v))); return d;
}
__device__ __forceinline__ void fma2(u64 &acc, u64 a, u64 b) {
    asm("fma.rn.f32x2 %0, %1, %2, %3;" : "=l"(acc) : "l"(a), "l"(b), "l"(acc));
}
__device__ __forceinline__ u64 mul2(u64 a, u64 b) {
    u64 d; asm("mul.rn.f32x2 %0, %1, %2;" : "=l"(d) : "l"(a), "l"(b)); return d;
}
__device__ __forceinline__ float2 unpack2(u64 v) {
    unsigned lo, hi;
    asm("mov.b64 {%0, %1}, %2;" : "=r"(lo), "=r"(hi) : "l"(v));
    return make_float2(__uint_as_float(lo), __uint_as_float(hi));
}
__device__ __forceinline__ float warpSum(float v) {
    #pragma unroll
    for (int o = 16; o > 0; o >>= 1) v += __shfl_xor_sync(0xffffffffu, v, o);
    return v;
}

// ---------------- small kernels -----------------------------------------------
__global__ void init_kernel() {
    int i = blockIdx.x * blockDim.x + threadIdx.x;
    if (i < Bq * Tn) g_colsum[i] = 0.0f;
}

__global__ __launch_bounds__(256) void rowocc_kernel(const float* __restrict__ tmask,
                                                     const float* __restrict__ qtmask) {
    int warp = threadIdx.x >> 5, lane = threadIdx.x & 31;
    int row = blockIdx.x * 8 + warp;
    if (row >= Bq * Qn) return;
    int b = row / Qn;
    float acc = 0.0f;
    const float* qt = qtmask + (size_t)row * Tn;
    const float* tm = tmask + (size_t)b * Tn;
    for (int t = lane; t < Tn; t += 32)
        acc += 1.0f - fmaxf(tm[t], qt[t]);
    acc = warpSum(acc);
    if (lane == 0) g_rowocc[row] = acc;
}

__global__ __launch_bounds__(256) void colact_kernel(const float* __restrict__ tmask,
                                                     const float* __restrict__ qtmask) {
    int b = blockIdx.y;
    int t = blockIdx.x * blockDim.x + threadIdx.x;
    if (t >= Tn) return;
    float tmv = tmask[b * Tn + t];
    float mx = -1e30f;
    for (int q = 0; q < Qn; q++) {
        float occ = 1.0f - fmaxf(tmv, qtmask[((size_t)(b * Qn + q)) * Tn + t]);
        mx = fmaxf(mx, occ);
    }
    g_colact[b * Tn + t] = mx;
}

// ---------------- QKV projection: pipelined 128x128 tiles, dup-A, f32x2 -------
// grid (32, 24): y<8 -> Q cols y*128; [8,16) -> K; [16,24) -> V
__global__ __launch_bounds__(256) void proj3_kernel(const float* __restrict__ qin,
                                                    const float* __restrict__ kvin,
                                                    const float* __restrict__ wq,
                                                    const float* __restrict__ wk,
                                                    const float* __restrict__ wv) {
    __shared__ float Ad[2][16][256];    // A dup'd: [k][2*row+{0,1}]
    __shared__ float Bsm[2][16][128];
    int y = blockIdx.y;
    int grp = (y < 8) ? 0 : ((y < 16) ? 1 : 2);
    int cn = (y - grp * 8) * 128;
    const float* A = grp ? kvin : qin;
    const float* W = (grp == 0) ? wq : (grp == 1) ? wk : wv;
    float* C = (grp == 0) ? g_q : (grp == 1) ? g_k : g_v;
    float scale = (grp == 0) ? 0.125f : 1.0f;
    int rowBase = blockIdx.x * 128;
    int tid = threadIdx.x, tx = tid & 15, ty = tid >> 4;
    int arow = tid >> 1, akh = (tid & 1) * 8;
    int r0 = tid >> 5, cs0 = (tid & 31) * 4;
    int f1 = tid + 256, r1 = f1 >> 5, cs1 = (f1 & 31) * 4;
    const float* Ap = &A[(size_t)(rowBase + arow) * Mn + akh];
    const float* Bp0 = &W[(size_t)((cn + cs0) >> 6) * 65536 + ((cn + cs0) & 63)];
    const float* Bp1 = &W[(size_t)((cn + cs1) >> 6) * 65536 + ((cn + cs1) & 63)];

    u64 acc[8][4];
    #pragma unroll
    for (int i = 0; i < 8; i++)
        #pragma unroll
        for (int j = 0; j < 4; j++) acc[i][j] = 0ull;

    float4 a0 = *(const float4*)(Ap);
    float4 a1 = *(const float4*)(Ap + 4);
    float4 b0 = *(const float4*)(Bp0 + (size_t)r0 * 64);
    float4 b1 = *(const float4*)(Bp1 + (size_t)r1 * 64);

    for (int c = 0; c < 64; c++) {
        int buf = c & 1;
        {
            float av[8] = {a0.x, a0.y, a0.z, a0.w, a1.x, a1.y, a1.z, a1.w};
            #pragma unroll
            for (int j = 0; j < 8; j++)
                *(float2*)&Ad[buf][akh + j][2 * arow] = make_float2(av[j], av[j]);
            *(float4*)&Bsm[buf][r0][cs0] = b0;
            *(float4*)&Bsm[buf][r1][cs1] = b1;
        }
        __syncthreads();
        if (c < 63) {
            int k0 = (c + 1) * 16;
            a0 = *(const float4*)(Ap + k0);
            a1 = *(const float4*)(Ap + k0 + 4);
            b0 = *(const float4*)(Bp0 + (size_t)(k0 + r0) * 64);
            b1 = *(const float4*)(Bp1 + (size_t)(k0 + r1) * 64);
        }
        #pragma unroll
        for (int kk = 0; kk < 16; kk++) {
            ulonglong2 A01 = *(const ulonglong2*)&Ad[buf][kk][ty * 16];
            ulonglong2 A23 = *(const ulonglong2*)&Ad[buf][kk][ty * 16 + 4];
            ulonglong2 A45 = *(const ulonglong2*)&Ad[buf][kk][ty * 16 + 8];
            ulonglong2 A67 = *(const ulonglong2*)&Ad[buf][kk][ty * 16 + 12];
            ulonglong2 B01 = *(const ulonglong2*)&Bsm[buf][kk][tx * 8];
            ulonglong2 B23 = *(const ulonglong2*)&Bsm[buf][kk][tx * 8 + 4];
            u64 ad[8] = {A01.x, A01.y, A23.x, A23.y, A45.x, A45.y, A67.x, A67.y};
            #pragma unroll
            for (int i = 0; i < 8; i++) {
                fma2(acc[i][0], ad[i], B01.x);
                fma2(acc[i][1], ad[i], B01.y);
                fma2(acc[i][2], ad[i], B23.x);
                fma2(acc[i][3], ad[i], B23.y);
            }
        }
    }
    #pragma unroll
    for (int i = 0; i < 8; i++) {
        int r = rowBase + ty * 8 + i;
        int b = r >> 10, qq = r & 1023;
        #pragma unroll
        for (int j = 0; j < 4; j++) {
            int cc = cn + tx * 8 + j * 2;
            int h = cc >> 6, d = cc & 63;
            float2 v = unpack2(acc[i][j]);
            float* dst = &C[(((size_t)(b * Hn + h)) * Qn + qq) * Kd + d];
            dst[0] = v.x * scale;
            dst[1] = v.y * scale;
        }
    }
}

// ---------------- output projection: pipelined, dup-A, f32x2 ------------------
__global__ __launch_bounds__(256) void outproj3_kernel(const float* __restrict__ qmask,
                                                       const float* __restrict__ wo,
                                                       float* __restrict__ out) {
    __shared__ float Ad[2][16][256];
    __shared__ float Bsm[2][16][128];
    int rowBase = blockIdx.x * 128;
    int cn = blockIdx.y * 128;
    int tid = threadIdx.x, tx = tid & 15, ty = tid >> 4;
    int arow = tid >> 1, akh = (tid & 1) * 8;
    int r0 = tid >> 5, cs0 = (tid & 31) * 4;
    int f1 = tid + 256, r1 = f1 >> 5, cs1 = (f1 & 31) * 4;
    const float* Ap = &g_preF[(size_t)(rowBase + arow) * 1024 + akh];
    const float* Bp0 = &wo[cn + cs0];
    const float* Bp1 = &wo[cn + cs1];

    u64 acc[8][4];
    #pragma unroll
    for (int i = 0; i < 8; i++)
        #pragma unroll
        for (int j = 0; j < 4; j++) acc[i][j] = 0ull;

    float4 a0 = *(const float4*)(Ap);
    float4 a1 = *(const float4*)(Ap + 4);
    float4 b0 = *(const float4*)(Bp0 + (size_t)r0 * 1024);
    float4 b1 = *(const float4*)(Bp1 + (size_t)r1 * 1024);

    for (int c = 0; c < 64; c++) {
        int buf = c & 1;
        {
            float av[8] = {a0.x, a0.y, a0.z, a0.w, a1.x, a1.y, a1.z, a1.w};
            #pragma unroll
            for (int j = 0; j < 8; j++)
                *(float2*)&Ad[buf][akh + j][2 * arow] = make_float2(av[j], av[j]);
            *(float4*)&Bsm[buf][r0][cs0] = b0;
            *(float4*)&Bsm[buf][r1][cs1] = b1;
        }
        __syncthreads();
        if (c < 63) {
            int k0 = (c + 1) * 16;
            a0 = *(const float4*)(Ap + k0);
            a1 = *(const float4*)(Ap + k0 + 4);
            b0 = *(const float4*)(Bp0 + (size_t)(k0 + r0) * 1024);
            b1 = *(const float4*)(Bp1 + (size_t)(k0 + r1) * 1024);
        }
        #pragma unroll
        for (int kk = 0; kk < 16; kk++) {
            ulonglong2 A01 = *(const ulonglong2*)&Ad[buf][kk][ty * 16];
            ulonglong2 A23 = *(const ulonglong2*)&Ad[buf][kk][ty * 16 + 4];
            ulonglong2 A45 = *(const ulonglong2*)&Ad[buf][kk][ty * 16 + 8];
            ulonglong2 A67 = *(const ulonglong2*)&Ad[buf][kk][ty * 16 + 12];
            ulonglong2 B01 = *(const ulonglong2*)&Bsm[buf][kk][tx * 8];
            ulonglong2 B23 = *(const ulonglong2*)&Bsm[buf][kk][tx * 8 + 4];
            u64 ad[8] = {A01.x, A01.y, A23.x, A23.y, A45.x, A45.y, A67.x, A67.y};
            #pragma unroll
            for (int i = 0; i < 8; i++) {
                fma2(acc[i][0], ad[i], B01.x);
                fma2(acc[i][1], ad[i], B01.y);
                fma2(acc[i][2], ad[i], B23.x);
                fma2(acc[i][3], ad[i], B23.y);
            }
        }
    }
    #pragma unroll
    for (int i = 0; i < 8; i++) {
        int r = rowBase + ty * 8 + i;
        float w = 1.0f - qmask[r];
        #pragma unroll
        for (int j = 0; j < 4; j++) {
            int cc = cn + tx * 8 + j * 2;
            float2 v = unpack2(acc[i][j]);
            out[(size_t)r * 1024 + cc]     = v.x * w;
            out[(size_t)r * 1024 + cc + 1] = v.y * w;
        }
    }
}

// ---------------- flash attention: dup Q/P operands, full-tile fast path ------
__global__ __launch_bounds__(256) void attn3_kernel(const float* __restrict__ tmask,
                                                    const float* __restrict__ qtmask) {
    extern __shared__ float smem[];
    float (*Qs)[132] = (float(*)[132])smem;                        // [d][2q dup]
    float (*Ks)[68]  = (float(*)[68])(smem + 64 * 132);            // [d][t]
    float* Vs        = smem + 64 * 132 + 64 * 68;                  // [t][d]
    float (*Ps)[132] = (float(*)[132])(smem + 64 * 132 + 64 * 68 + 64 * 64); // [t][2q dup]

    int b = blockIdx.z, h = blockIdx.y;
    int qb = (gridDim.x - 1 - blockIdx.x) * 64;
    int bh = b * Hn + h;
    int tid = threadIdx.x, tx = tid & 15, ty = tid >> 4;

    const float* qsrc = g_q + ((size_t)bh * Qn + qb) * Kd;
    #pragma unroll
    for (int it = 0; it < 4; it++) {
        int f = it * 256 + tid;
        int q = f >> 4, ds = (f & 15) * 4;
        float4 v = *(const float4*)&qsrc[q * Kd + ds];
        Qs[ds + 0][2 * q] = v.x; Qs[ds + 0][2 * q + 1] = v.x;
        Qs[ds + 1][2 * q] = v.y; Qs[ds + 1][2 * q + 1] = v.y;
        Qs[ds + 2][2 * q] = v.z; Qs[ds + 2][2 * q + 1] = v.z;
        Qs[ds + 3][2 * q] = v.w; Qs[ds + 3][2 * q + 1] = v.w;
    }

    float m[4], l[4];
    u64 od[4][2];
    #pragma unroll
    for (int i = 0; i < 4; i++) { m[i] = -1e30f; l[i] = 0.0f; od[i][0] = 0ull; od[i][1] = 0ull; }

    const float* kbase = g_k + (size_t)bh * Tn * Kd;
    const float* vbase = g_v + (size_t)bh * Tn * Vd;
    int nt = qb / 64 + 1;

    for (int tile = 0; tile < nt; tile++) {
        int t0 = tile * 64;
        __syncthreads();
        #pragma unroll
        for (int it = 0; it < 4; it++) {
            int f = it * 256 + tid;
            int t = f >> 4, ds = (f & 15) * 4;
            float4 kv = *(const float4*)&kbase[(size_t)(t0 + t) * Kd + ds];
            Ks[ds + 0][t] = kv.x; Ks[ds + 1][t] = kv.y; Ks[ds + 2][t] = kv.z; Ks[ds + 3][t] = kv.w;
            *(float4*)&Vs[f * 4] = *(const float4*)&vbase[(size_t)t0 * Vd + f * 4];
        }
        __syncthreads();

        // ---- S = Q K^T ----
        u64 sd[4][2];
        #pragma unroll
        for (int i = 0; i < 4; i++) { sd[i][0] = 0ull; sd[i][1] = 0ull; }
        #pragma unroll 8
        for (int d = 0; d < 64; d++) {
            ulonglong2 q01 = *(const ulonglong2*)&Qs[d][ty * 8];
            ulonglong2 q23 = *(const ulonglong2*)&Qs[d][ty * 8 + 4];
            ulonglong2 kp  = *(const ulonglong2*)&Ks[d][tx * 4];
            fma2(sd[0][0], q01.x, kp.x); fma2(sd[0][1], q01.x, kp.y);
            fma2(sd[1][0], q01.y, kp.x); fma2(sd[1][1], q01.y, kp.y);
            fma2(sd[2][0], q23.x, kp.x); fma2(sd[2][1], q23.x, kp.y);
            fma2(sd[3][0], q23.y, kp.x); fma2(sd[3][1], q23.y, kp.y);
        }
        float S[4][4];
        #pragma unroll
        for (int i = 0; i < 4; i++) {
            float2 v0 = unpack2(sd[i][0]), v1 = unpack2(sd[i][1]);
            S[i][0] = v0.x; S[i][1] = v0.y; S[i][2] = v1.x; S[i][3] = v1.y;
        }

        if (tile < nt - 1) {
            // fully-active tile: no mask loads, no clamps
            #pragma unroll
            for (int i = 0; i < 4; i++) {
                float rmax = fmaxf(fmaxf(S[i][0], S[i][1]), fmaxf(S[i][2], S[i][3]));
                #pragma unroll
                for (int o = 8; o > 0; o >>= 1)
                    rmax = fmaxf(rmax, __shfl_xor_sync(0xffffffffu, rmax, o));
                float mnew = fmaxf(m[i], rmax);
                float sc = __expf(m[i] - mnew);
                float p[4], ps;
                p[0] = __expf(S[i][0] - mnew); p[1] = __expf(S[i][1] - mnew);
                p[2] = __expf(S[i][2] - mnew); p[3] = __expf(S[i][3] - mnew);
                ps = p[0] + p[1] + p[2] + p[3];
                #pragma unroll
                for (int o = 8; o > 0; o >>= 1)
                    ps += __shfl_xor_sync(0xffffffffu, ps, o);
                l[i] = l[i] * sc + ps;
                m[i] = mnew;
                u64 scd = dup2(sc);
                od[i][0] = mul2(od[i][0], scd);
                od[i][1] = mul2(od[i][1], scd);
                int qc = (ty * 4 + i) * 2;
                *(float2*)&Ps[tx * 4 + 0][qc] = make_float2(p[0], p[0]);
                *(float2*)&Ps[tx * 4 + 1][qc] = make_float2(p[1], p[1]);
                *(float2*)&Ps[tx * 4 + 2][qc] = make_float2(p[2], p[2]);
                *(float2*)&Ps[tx * 4 + 3][qc] = make_float2(p[3], p[3]);
            }
        } else {
            float4 tm4 = *(const float4*)&tmask[b * Tn + t0 + tx * 4];
            float tma[4] = {tm4.x, tm4.y, tm4.z, tm4.w};
            #pragma unroll
            for (int i = 0; i < 4; i++) {
                int qg = qb + ty * 4 + i;
                float4 qt4 = *(const float4*)&qtmask[((size_t)(b * Qn + qg)) * Tn + t0 + tx * 4];
                float qta[4] = {qt4.x, qt4.y, qt4.z, qt4.w};
                float rmax = -1e30f;
                bool act[4];
                #pragma unroll
                for (int j = 0; j < 4; j++) {
                    act[j] = (1.0f - fmaxf(tma[j], qta[j])) > 0.0f;
                    S[i][j] = act[j] ? S[i][j] : -1e30f;
                    rmax = fmaxf(rmax, S[i][j]);
                }
                #pragma unroll
                for (int o = 8; o > 0; o >>= 1)
                    rmax = fmaxf(rmax, __shfl_xor_sync(0xffffffffu, rmax, o));
                float mnew = fmaxf(m[i], rmax);
                float sc = __expf(m[i] - mnew);
                float p[4], ps = 0.0f;
                #pragma unroll
                for (int j = 0; j < 4; j++) {
                    p[j] = act[j] ? __expf(S[i][j] - mnew) : 0.0f;
                    ps += p[j];
                }
                #pragma unroll
                for (int o = 8; o > 0; o >>= 1)
                    ps += __shfl_xor_sync(0xffffffffu, ps, o);
                l[i] = l[i] * sc + ps;
                m[i] = mnew;
                u64 scd = dup2(sc);
                od[i][0] = mul2(od[i][0], scd);
                od[i][1] = mul2(od[i][1], scd);
                int qc = (ty * 4 + i) * 2;
                *(float2*)&Ps[tx * 4 + 0][qc] = make_float2(p[0], p[0]);
                *(float2*)&Ps[tx * 4 + 1][qc] = make_float2(p[1], p[1]);
                *(float2*)&Ps[tx * 4 + 2][qc] = make_float2(p[2], p[2]);
                *(float2*)&Ps[tx * 4 + 3][qc] = make_float2(p[3], p[3]);
            }
        }
        __syncthreads();

        // ---- O += P V ----
        #pragma unroll 8
        for (int t = 0; t < 64; t++) {
            ulonglong2 p01 = *(const ulonglong2*)&Ps[t][ty * 8];
            ulonglong2 p23 = *(const ulonglong2*)&Ps[t][ty * 8 + 4];
            ulonglong2 vp  = *(const ulonglong2*)&Vs[t * 64 + tx * 4];
            fma2(od[0][0], p01.x, vp.x); fma2(od[0][1], p01.x, vp.y);
            fma2(od[1][0], p01.y, vp.x); fma2(od[1][1], p01.y, vp.y);
            fma2(od[2][0], p23.x, vp.x); fma2(od[2][1], p23.x, vp.y);
            fma2(od[3][0], p23.y, vp.x); fma2(od[3][1], p23.y, vp.y);
        }
    }

    #pragma unroll
    for (int i = 0; i < 4; i++) {
        int qg = qb + ty * 4 + i;
        float inv = 1.0f / l[i];
        float2 v0 = unpack2(od[i][0]), v1 = unpack2(od[i][1]);
        float4 o = make_float4(v0.x * inv, v0.y * inv, v1.x * inv, v1.y * inv);
        *(float4*)&g_preF[((size_t)(b * Qn + qg)) * 1024 + h * 64 + tx * 4] = o;
        if (tx == 0) {
            g_m[bh * Qn + qg] = m[i];
            g_l[bh * Qn + qg] = l[i];
        }
    }
}

// ---------------- column sums pass 2 (fast path for full q-tiles) -------------
__global__ __launch_bounds__(256) void colsum_kernel(const float* __restrict__ tmask,
                                                     const float* __restrict__ qtmask) {
    __shared__ float ksh[32][64];
    __shared__ float qsh[64][65];
    __shared__ float msh[64], lsh[64], rsh[64];
    int b = blockIdx.z, h = blockIdx.y;
    int tb = blockIdx.x * 32;
    int tid = threadIdx.x, lane = tid & 31, warp = tid >> 5;

    const float* kbase = g_k + ((size_t)(b * Hn + h) * Tn + tb) * Kd;
    for (int e = tid * 4; e < 32 * 64; e += 1024)
        *(float4*)&((float*)ksh)[e] = *(const float4*)&kbase[e];

    float csum[4] = {0, 0, 0, 0};
    int hq = (b * Hn + h) * Qn;
    const float* qmat = g_q + (size_t)hq * Kd;
    int qstart = (tb / 64) * 64;

    for (int q0 = qstart; q0 < Qn; q0 += 64) {
        __syncthreads();
        for (int e = tid * 4; e < 64 * 64; e += 1024) {
            int qq = e >> 6, d = e & 63;
            float4 v = *(const float4*)&qmat[(size_t)q0 * 64 + e];
            qsh[qq][d + 0] = v.x; qsh[qq][d + 1] = v.y; qsh[qq][d + 2] = v.z; qsh[qq][d + 3] = v.w;
        }
        if (tid < 64) {
            msh[tid] = g_m[hq + q0 + tid];
            lsh[tid] = g_l[hq + q0 + tid];
            rsh[tid] = g_rowocc[b * Qn + q0 + tid];
        }
        __syncthreads();

        float s0[4] = {0, 0, 0, 0}, s1[4] = {0, 0, 0, 0};
        #pragma unroll 16
        for (int d = 0; d < 64; d++) {
            float qv0 = qsh[lane][d], qv1 = qsh[lane + 32][d];
            #pragma unroll
            for (int i = 0; i < 4; i++) {
                float kv = ksh[warp * 4 + i][d];
                s0[i] += kv * qv0;
                s1[i] += kv * qv1;
            }
        }
        if (q0 == qstart) {
            // partial tile: exact mask handling
            #pragma unroll
            for (int i = 0; i < 4; i++) {
                int t = tb + warp * 4 + i;
                float tmv = tmask[b * Tn + t];
                int qg0 = q0 + lane, qg1 = q0 + lane + 32;
                float occ0 = 1.0f - fmaxf(tmv, qtmask[(size_t)(b * Qn + qg0) * Tn + t]);
                float occ1 = 1.0f - fmaxf(tmv, qtmask[(size_t)(b * Qn + qg1) * Tn + t]);
                if (occ0 > 0.0f) csum[i] += __expf(s0[i] - msh[lane]) / lsh[lane] * rsh[lane];
                if (occ1 > 0.0f) csum[i] += __expf(s1[i] - msh[lane + 32]) / lsh[lane + 32] * rsh[lane + 32];
            }
        } else {
            // fully-active q-tile: no mask loads, no branches
            #pragma unroll
            for (int i = 0; i < 4; i++) {
                csum[i] += __expf(s0[i] - msh[lane]) / lsh[lane] * rsh[lane]
                         + __expf(s1[i] - msh[lane + 32]) / lsh[lane + 32] * rsh[lane + 32];
            }
        }
    }
    #pragma unroll
    for (int i = 0; i < 4; i++) {
        float v = warpSum(csum[i]);
        if (lane == 0) atomicAdd(&g_colsum[b * Tn + tb + warp * 4 + i], v);
    }
}

// ---------------- entropy ------------------------------------------------------
__global__ __launch_bounds__(256) void entropy_kernel(float* __restrict__ eout) {
    int b = blockIdx.x, tid = threadIdx.x;
    int lane = tid & 31, warp = tid >> 5;
    __shared__ float sh0[8], sh1[8];
    float sm = 0.0f, sa = 0.0f;
    for (int t = tid; t < Tn; t += 256) {
        sm += g_colsum[b * Tn + t];
        sa += g_colact[b * Tn + t];
    }
    sm = warpSum(sm); sa = warpSum(sa);
    if (lane == 0) { sh0[warp] = sm; sh1[warp] = sa; }
    __syncthreads();
    float tsum = 0.0f, csum = 0.0f;
    #pragma unroll
    for (int w = 0; w < 8; w++) { tsum += sh0[w]; csum += sh1[w]; }
    __syncthreads();
    float ent = 0.0f;
    for (int t = tid; t < Tn; t += 256) {
        float p = g_colsum[b * Tn + t] / tsum;
        if (g_colact[b * Tn + t] > 0.0f && p > 0.0f) ent -= p * log2f(p);
    }
    ent = warpSum(ent);
    if (lane == 0) sh0[warp] = ent;
    __syncthreads();
    if (tid == 0) {
        float e = 0.0f;
        #pragma unroll
        for (int w = 0; w < 8; w++) e += sh0[w];
        eout[b] = e / log2f(csum);
    }
}

// ---------------- launch -------------------------------------------------------
extern "C" void kernel_launch(void* const* d_in, const int* in_sizes, int n_in,
                              void* d_out, int out_size) {
    const float* qinput  = (const float*)d_in[0];
    const float* kvinput = (const float*)d_in[1];
    const float* qmask   = (const float*)d_in[2];
    const float* tmask   = (const float*)d_in[3];
    const float* qtmask  = (const float*)d_in[4];
    const float* wq      = (const float*)d_in[5];
    const float* wk      = (const float*)d_in[6];
    const float* wv      = (const float*)d_in[7];
    const float* wo      = (const float*)d_in[8];
    float* out  = (float*)d_out;
    float* eout = out + (out_size - Bq);

    const int ATTN_SMEM = (64 * 132 + 64 * 68 + 64 * 64 + 64 * 132) * 4;  // 101376 B
    cudaFuncSetAttribute(attn3_kernel, cudaFuncAttributeMaxDynamicSharedMemorySize, ATTN_SMEM);

    init_kernel<<<(Bq * Tn + 255) / 256, 256>>>();
    rowocc_kernel<<<(Bq * Qn) / 8, 256>>>(tmask, qtmask);
    colact_kernel<<<dim3(Tn / 256, Bq), 256>>>(tmask, qtmask);
    proj3_kernel<<<dim3(32, 24), 256>>>(qinput, kvinput, wq, wk, wv);
    attn3_kernel<<<dim3(Qn / 64, Hn, Bq), 256, ATTN_SMEM>>>(tmask, qtmask);
    colsum_kernel<<<dim3(Tn / 32, Hn, Bq), 256>>>(tmask, qtmask);
    entropy_kernel<<<Bq, 256>>>(eout);
    outproj3_kernel<<<dim3(32, 8), 256>>>(qmask, wo, out);
}

// round 11
// speedup vs baseline: 1.4715x; 1.4715x over previous
#include <cuda_runtime.h>
#include <cuda_bf16.h>
#include <math.h>
#include <stdint.h>

#define Bq 4
#define Qn 1024
#define Tn 1024
#define Hn 16
#define Mn 1024
#define Kd 64
#define Vd 64

typedef unsigned long long u64;

// ---------------- scratch (static device globals; no runtime alloc) ----------
__device__ float g_q[Bq*Hn*Qn*Kd];
__device__ float g_k[Bq*Hn*Tn*Kd];
__device__ float g_v[Bq*Hn*Tn*Vd];
__device__ float g_preF[Bq*Qn*Hn*Vd];  // [b*1024+q][h*64+d]
__device__ float g_m[Bq*Hn*Qn];
__device__ float g_l[Bq*Hn*Qn];
__device__ float g_rowocc[Bq*Qn];
__device__ float g_colact[Bq*Tn];
__device__ float g_colsum[Bq*Tn];

// bf16 hi/lo operands (row-major, k-contiguous, 1024 per row)
__device__ __align__(16) __nv_bfloat16 cAq_h[4096*1024],  cAq_l[4096*1024];
__device__ __align__(16) __nv_bfloat16 cAkv_h[4096*1024], cAkv_l[4096*1024];
__device__ __align__(16) __nv_bfloat16 cApre_h[4096*1024],cApre_l[4096*1024];
__device__ __align__(16) __nv_bfloat16 cBq_h[1024*1024],  cBq_l[1024*1024];
__device__ __align__(16) __nv_bfloat16 cBk_h[1024*1024],  cBk_l[1024*1024];
__device__ __align__(16) __nv_bfloat16 cBv_h[1024*1024],  cBv_l[1024*1024];
__device__ __align__(16) __nv_bfloat16 cBo_h[1024*1024],  cBo_l[1024*1024];

// ---------------- helpers ------------------------------------------------------
__device__ __forceinline__ uint32_t smem_u32(const void* p) {
    uint32_t a;
    asm("{ .reg .u64 t; cvta.to.shared.u64 t, %1; cvt.u32.u64 %0, t; }" : "=r"(a) : "l"(p));
    return a;
}
__device__ __forceinline__ void split2(float x, unsigned short &h, unsigned short &l) {
    __nv_bfloat16 hb = __float2bfloat16(x);
    float r = x - __bfloat162float(hb);
    __nv_bfloat16 lb = __float2bfloat16(r);
    h = __bfloat16_as_ushort(hb);
    l = __bfloat16_as_ushort(lb);
}
__device__ __forceinline__ u64 dup2(float v) {
    u64 d; asm("mov.b64 %0, {%1, %1};" : "=l"(d) : "r"(__float_as_uint(v))); return d;
}
__device__ __forceinline__ void fma2(u64 &acc, u64 a, u64 b) {
    asm("fma.rn.f32x2 %0, %1, %2, %3;" : "=l"(acc) : "l"(a), "l"(b), "l"(acc));
}
__device__ __forceinline__ u64 mul2(u64 a, u64 b) {
    u64 d; asm("mul.rn.f32x2 %0, %1, %2;" : "=l"(d) : "l"(a), "l"(b)); return d;
}
__device__ __forceinline__ float2 unpack2(u64 v) {
    unsigned lo, hi;
    asm("mov.b64 {%0, %1}, %2;" : "=r"(lo), "=r"(hi) : "l"(v));
    return make_float2(__uint_as_float(lo), __uint_as_float(hi));
}
__device__ __forceinline__ float warpSum(float v) {
    #pragma unroll
    for (int o = 16; o > 0; o >>= 1) v += __shfl_xor_sync(0xffffffffu, v, o);
    return v;
}
#define LDX4(r0, r1, r2, r3, addr) \
    asm volatile("ldmatrix.sync.aligned.m8n8.x4.shared.b16 {%0,%1,%2,%3}, [%4];" \
        : "=r"(r0), "=r"(r1), "=r"(r2), "=r"(r3) : "r"(addr))
#define MMA16816(d, a, b) \
    asm volatile("mma.sync.aligned.m16n8k16.row.col.f32.bf16.bf16.f32 " \
        "{%0,%1,%2,%3}, {%4,%5,%6,%7}, {%8,%9}, {%0,%1,%2,%3};" \
        : "+f"((d)[0]), "+f"((d)[1]), "+f"((d)[2]), "+f"((d)[3]) \
        : "r"((a)[0]), "r"((a)[1]), "r"((a)[2]), "r"((a)[3]), "r"((b)[0]), "r"((b)[1]))

// ---------------- small kernels -------------------------------------------------
__global__ void init_kernel() {
    int i = blockIdx.x * blockDim.x + threadIdx.x;
    if (i < Bq * Tn) g_colsum[i] = 0.0f;
}

__global__ __launch_bounds__(256) void rowocc_kernel(const float* __restrict__ tmask,
                                                     const float* __restrict__ qtmask) {
    int warp = threadIdx.x >> 5, lane = threadIdx.x & 31;
    int row = blockIdx.x * 8 + warp;
    if (row >= Bq * Qn) return;
    int b = row / Qn;
    float acc = 0.0f;
    const float* qt = qtmask + (size_t)row * Tn;
    const float* tm = tmask + (size_t)b * Tn;
    for (int t = lane; t < Tn; t += 32)
        acc += 1.0f - fmaxf(tm[t], qt[t]);
    acc = warpSum(acc);
    if (lane == 0) g_rowocc[row] = acc;
}

__global__ __launch_bounds__(256) void colact_kernel(const float* __restrict__ tmask,
                                                     const float* __restrict__ qtmask) {
    int b = blockIdx.y;
    int t = blockIdx.x * blockDim.x + threadIdx.x;
    if (t >= Tn) return;
    float tmv = tmask[b * Tn + t];
    float mx = -1e30f;
    for (int q = 0; q < Qn; q++) {
        float occ = 1.0f - fmaxf(tmv, qtmask[((size_t)(b * Qn + q)) * Tn + t]);
        mx = fmaxf(mx, occ);
    }
    g_colact[b * Tn + t] = mx;
}

// ---------------- conversions ---------------------------------------------------
// A matrices: [4096][1024] f32 -> hi/lo bf16 row-major
__global__ __launch_bounds__(256) void convA2_kernel(const float* __restrict__ srcp, int sel) {
    const float* src = srcp;
    __nv_bfloat16 *dh, *dl;
    if (sel == 0)      { dh = cAq_h;  dl = cAq_l;  }
    else if (sel == 1) { dh = cAkv_h; dl = cAkv_l; }
    else               { src = g_preF; dh = cApre_h; dl = cApre_l; }
    size_t i4 = ((size_t)blockIdx.x * 256 + threadIdx.x) * 4;
    float4 v = *(const float4*)&src[i4];
    unsigned short h0, l0, h1, l1, h2, l2, h3, l3;
    split2(v.x, h0, l0); split2(v.y, h1, l1); split2(v.z, h2, l2); split2(v.w, h3, l3);
    uint2 ph = make_uint2(((unsigned)h1 << 16) | h0, ((unsigned)h3 << 16) | h2);
    uint2 pl = make_uint2(((unsigned)l1 << 16) | l0, ((unsigned)l3 << 16) | l2);
    *(uint2*)&dh[i4] = ph;
    *(uint2*)&dl[i4] = pl;
}

// wq/wk/wv [h][m][d] -> Bt[n=h*64+d][k=m]; kscale folded into wq
__global__ __launch_bounds__(256) void convW2_kernel(const float* __restrict__ wq_,
                                                     const float* __restrict__ wk_,
                                                     const float* __restrict__ wv_) {
    __shared__ float st[64][65];
    int z = blockIdx.z, h = blockIdx.x, mc = blockIdx.y;
    const float* W = (z == 0) ? wq_ : (z == 1) ? wk_ : wv_;
    __nv_bfloat16* dh = (z == 0) ? cBq_h : (z == 1) ? cBk_h : cBv_h;
    __nv_bfloat16* dl = (z == 0) ? cBq_l : (z == 1) ? cBk_l : cBv_l;
    float sc = (z == 0) ? 0.125f : 1.0f;
    int tid = threadIdx.x;
    #pragma unroll
    for (int i = 0; i < 4; i++) {
        int e = tid + i * 256;
        int mm = e >> 4, d4 = (e & 15) * 4;
        float4 v = *(const float4*)&W[(size_t)h * 65536 + (size_t)(mc * 64 + mm) * 64 + d4];
        st[mm][d4] = v.x * sc; st[mm][d4 + 1] = v.y * sc;
        st[mm][d4 + 2] = v.z * sc; st[mm][d4 + 3] = v.w * sc;
    }
    __syncthreads();
    int d = tid >> 2, mg = (tid & 3) * 16;
    unsigned ph[8], pl[8];
    #pragma unroll
    for (int j = 0; j < 8; j++) {
        unsigned short ha, la, hb, lb;
        split2(st[mg + 2 * j][d], ha, la);
        split2(st[mg + 2 * j + 1][d], hb, lb);
        ph[j] = ((unsigned)hb << 16) | ha;
        pl[j] = ((unsigned)lb << 16) | la;
    }
    size_t base = (size_t)(h * 64 + d) * 1024 + mc * 64 + mg;
    *(uint4*)&dh[base]     = make_uint4(ph[0], ph[1], ph[2], ph[3]);
    *(uint4*)&dh[base + 8] = make_uint4(ph[4], ph[5], ph[6], ph[7]);
    *(uint4*)&dl[base]     = make_uint4(pl[0], pl[1], pl[2], pl[3]);
    *(uint4*)&dl[base + 8] = make_uint4(pl[4], pl[5], pl[6], pl[7]);
}

// wo [h][v][m] -> Bt[n=m][k=h*64+v]
__global__ __launch_bounds__(256) void convWo2_kernel(const float* __restrict__ wo) {
    __shared__ float st[64][65];
    int h = blockIdx.x, mc = blockIdx.y;
    int tid = threadIdx.x;
    #pragma unroll
    for (int i = 0; i < 4; i++) {
        int e = tid + i * 256;
        int v = e >> 4, m4 = (e & 15) * 4;
        float4 x = *(const float4*)&wo[(size_t)(h * 64 + v) * 1024 + mc * 64 + m4];
        st[v][m4] = x.x; st[v][m4 + 1] = x.y; st[v][m4 + 2] = x.z; st[v][m4 + 3] = x.w;
    }
    __syncthreads();
    int mm = tid >> 2, vg = (tid & 3) * 16;
    unsigned ph[8], pl[8];
    #pragma unroll
    for (int j = 0; j < 8; j++) {
        unsigned short ha, la, hb, lb;
        split2(st[vg + 2 * j][mm], ha, la);
        split2(st[vg + 2 * j + 1][mm], hb, lb);
        ph[j] = ((unsigned)hb << 16) | ha;
        pl[j] = ((unsigned)lb << 16) | la;
    }
    size_t base = (size_t)(mc * 64 + mm) * 1024 + h * 64 + vg;
    *(uint4*)&cBo_h[base]     = make_uint4(ph[0], ph[1], ph[2], ph[3]);
    *(uint4*)&cBo_h[base + 8] = make_uint4(ph[4], ph[5], ph[6], ph[7]);
    *(uint4*)&cBo_l[base]     = make_uint4(pl[0], pl[1], pl[2], pl[3]);
    *(uint4*)&cBo_l[base + 8] = make_uint4(pl[4], pl[5], pl[6], pl[7]);
}

// ---------------- HMMA GEMM: C[4096x1024] = A[4096xK] x Bt^T, hi/lo bf16 split --
// 128x128 tile, 8 warps (2x4), each 64x32. K chunks of 32, cp.async double buffer.
// smem row stride 40 bf16 (80B). Arrays per buf: Ah(0) Al(10240) Bh(20480) Bl(30720).
__device__ __forceinline__ void hg_prefetch(uint32_t sbuf,
        const __nv_bfloat16* Ah, const __nv_bfloat16* Al,
        const __nv_bfloat16* Bh, const __nv_bfloat16* Bl,
        int rowBase, int cn, int k0, int tid) {
    #pragma unroll
    for (int j = 0; j < 8; j++) {
        int lin = j * 256 + tid;
        int arr = lin >> 9, within = lin & 511;
        int row = within >> 2, seg = within & 3;
        const __nv_bfloat16* g;
        if (arr == 0)      g = Ah + (size_t)(rowBase + row) * 1024;
        else if (arr == 1) g = Al + (size_t)(rowBase + row) * 1024;
        else if (arr == 2) g = Bh + (size_t)(cn + row) * 1024;
        else               g = Bl + (size_t)(cn + row) * 1024;
        g += k0 + seg * 8;
        uint32_t s = sbuf + arr * 10240 + row * 80 + seg * 16;
        asm volatile("cp.async.cg.shared.global [%0], [%1], 16;" :: "r"(s), "l"(g));
    }
}

__global__ __launch_bounds__(256) void hgemm_kernel(int mode,
        const float* __restrict__ qmask, float* __restrict__ outp, int z) {
    extern __shared__ char sm[];
    uint32_t sb = smem_u32(sm);
    int tid = threadIdx.x, lane = tid & 31, wid = tid >> 5;
    int warp_m = wid & 1, warp_n = wid >> 1;

    const __nv_bfloat16 *Ah, *Al, *Bh, *Bl;
    float* C;
    if (mode == 0) {
        Ah = (z == 0) ? cAq_h : cAkv_h;
        Al = (z == 0) ? cAq_l : cAkv_l;
        Bh = (z == 0) ? cBq_h : (z == 1) ? cBk_h : cBv_h;
        Bl = (z == 0) ? cBq_l : (z == 1) ? cBk_l : cBv_l;
        C  = (z == 0) ? g_q : (z == 1) ? g_k : g_v;
    } else {
        Ah = cApre_h; Al = cApre_l; Bh = cBo_h; Bl = cBo_l; C = outp;
    }
    int rowBase = blockIdx.x * 128;
    int cn = blockIdx.y * 128;

    float acc[4][4][4];
    #pragma unroll
    for (int i = 0; i < 4; i++)
        #pragma unroll
        for (int j = 0; j < 4; j++)
            #pragma unroll
            for (int r = 0; r < 4; r++) acc[i][j][r] = 0.0f;

    int laneRow = lane & 15, laneK = lane >> 4;
    uint32_t aOff = (uint32_t)((warp_m * 64 + laneRow) * 80 + laneK * 16);
    uint32_t bOff = (uint32_t)(20480 + (warp_n * 32 + laneRow) * 80 + laneK * 16);

    hg_prefetch(sb, Ah, Al, Bh, Bl, rowBase, cn, 0, tid);
    asm volatile("cp.async.commit_group;");

    for (int c = 0; c < 32; c++) {
        uint32_t sbuf = sb + (c & 1) * 40960;
        if (c < 31) {
            hg_prefetch(sb + ((c + 1) & 1) * 40960, Ah, Al, Bh, Bl, rowBase, cn, (c + 1) * 32, tid);
            asm volatile("cp.async.commit_group;");
            asm volatile("cp.async.wait_group 1;");
        } else {
            asm volatile("cp.async.wait_group 0;");
        }
        __syncthreads();

        #pragma unroll
        for (int ks = 0; ks < 2; ks++) {
            uint32_t kOff = ks * 32;
            // B fragments: 4 n-tiles of 8, hi and lo
            unsigned bh[4][2], bl[4][2];
            {
                unsigned r0, r1, r2, r3;
                LDX4(r0, r1, r2, r3, sbuf + bOff + kOff);            // pair0 hi
                bh[0][0] = r0; bh[0][1] = r2; bh[1][0] = r1; bh[1][1] = r3;
                LDX4(r0, r1, r2, r3, sbuf + bOff + kOff + 1280);     // pair1 hi
                bh[2][0] = r0; bh[2][1] = r2; bh[3][0] = r1; bh[3][1] = r3;
                LDX4(r0, r1, r2, r3, sbuf + bOff + kOff + 10240);    // pair0 lo
                bl[0][0] = r0; bl[0][1] = r2; bl[1][0] = r1; bl[1][1] = r3;
                LDX4(r0, r1, r2, r3, sbuf + bOff + kOff + 11520);    // pair1 lo
                bl[2][0] = r0; bl[2][1] = r2; bl[3][0] = r1; bl[3][1] = r3;
            }
            #pragma unroll
            for (int mt = 0; mt < 4; mt++) {
                unsigned ah[4], al4[4];
                uint32_t aAddr = sbuf + aOff + kOff + mt * 1280;
                LDX4(ah[0], ah[1], ah[2], ah[3], aAddr);
                LDX4(al4[0], al4[1], al4[2], al4[3], aAddr + 10240);
                #pragma unroll
                for (int nt = 0; nt < 4; nt++) {
                    MMA16816(acc[mt][nt], ah, bh[nt]);
                    MMA16816(acc[mt][nt], ah, bl[nt]);
                    MMA16816(acc[mt][nt], al4, bh[nt]);
                }
            }
        }
        __syncthreads();
    }

    // epilogue
    int g = lane >> 2, tc = (lane & 3) * 2;
    #pragma unroll
    for (int mt = 0; mt < 4; mt++) {
        #pragma unroll
        for (int nt = 0; nt < 4; nt++) {
            int r0 = rowBase + warp_m * 64 + mt * 16 + g;
            int cc = cn + warp_n * 32 + nt * 8 + tc;
            if (mode == 0) {
                int h = cc >> 6, d = cc & 63;
                int b0 = r0 >> 10, q0 = r0 & 1023;
                float* d0 = &C[(((size_t)(b0 * Hn + h)) * Qn + q0) * Kd + d];
                *(float2*)d0 = make_float2(acc[mt][nt][0], acc[mt][nt][1]);
                int r1 = r0 + 8;
                int b1 = r1 >> 10, q1 = r1 & 1023;
                float* d1 = &C[(((size_t)(b1 * Hn + h)) * Qn + q1) * Kd + d];
                *(float2*)d1 = make_float2(acc[mt][nt][2], acc[mt][nt][3]);
            } else {
                float w0 = 1.0f - qmask[r0];
                float w1 = 1.0f - qmask[r0 + 8];
                *(float2*)&C[(size_t)r0 * 1024 + cc] =
                    make_float2(acc[mt][nt][0] * w0, acc[mt][nt][1] * w0);
                *(float2*)&C[(size_t)(r0 + 8) * 1024 + cc] =
                    make_float2(acc[mt][nt][2] * w1, acc[mt][nt][3] * w1);
            }
        }
    }
}

// ---------------- flash attention (R10 attn3, unchanged) ------------------------
__global__ __launch_bounds__(256) void attn3_kernel(const float* __restrict__ tmask,
                                                    const float* __restrict__ qtmask) {
    extern __shared__ float smem[];
    float (*Qs)[132] = (float(*)[132])smem;
    float (*Ks)[68]  = (float(*)[68])(smem + 64 * 132);
    float* Vs        = smem + 64 * 132 + 64 * 68;
    float (*Ps)[132] = (float(*)[132])(smem + 64 * 132 + 64 * 68 + 64 * 64);

    int b = blockIdx.z, h = blockIdx.y;
    int qb = (gridDim.x - 1 - blockIdx.x) * 64;
    int bh = b * Hn + h;
    int tid = threadIdx.x, tx = tid & 15, ty = tid >> 4;

    const float* qsrc = g_q + ((size_t)bh * Qn + qb) * Kd;
    #pragma unroll
    for (int it = 0; it < 4; it++) {
        int f = it * 256 + tid;
        int q = f >> 4, ds = (f & 15) * 4;
        float4 v = *(const float4*)&qsrc[q * Kd + ds];
        Qs[ds + 0][2 * q] = v.x; Qs[ds + 0][2 * q + 1] = v.x;
        Qs[ds + 1][2 * q] = v.y; Qs[ds + 1][2 * q + 1] = v.y;
        Qs[ds + 2][2 * q] = v.z; Qs[ds + 2][2 * q + 1] = v.z;
        Qs[ds + 3][2 * q] = v.w; Qs[ds + 3][2 * q + 1] = v.w;
    }

    float m[4], l[4];
    u64 od[4][2];
    #pragma unroll
    for (int i = 0; i < 4; i++) { m[i] = -1e30f; l[i] = 0.0f; od[i][0] = 0ull; od[i][1] = 0ull; }

    const float* kbase = g_k + (size_t)bh * Tn * Kd;
    const float* vbase = g_v + (size_t)bh * Tn * Vd;
    int nt = qb / 64 + 1;

    for (int tile = 0; tile < nt; tile++) {
        int t0 = tile * 64;
        __syncthreads();
        #pragma unroll
        for (int it = 0; it < 4; it++) {
            int f = it * 256 + tid;
            int t = f >> 4, ds = (f & 15) * 4;
            float4 kv = *(const float4*)&kbase[(size_t)(t0 + t) * Kd + ds];
            Ks[ds + 0][t] = kv.x; Ks[ds + 1][t] = kv.y; Ks[ds + 2][t] = kv.z; Ks[ds + 3][t] = kv.w;
            *(float4*)&Vs[f * 4] = *(const float4*)&vbase[(size_t)t0 * Vd + f * 4];
        }
        __syncthreads();

        u64 sd[4][2];
        #pragma unroll
        for (int i = 0; i < 4; i++) { sd[i][0] = 0ull; sd[i][1] = 0ull; }
        #pragma unroll 8
        for (int d = 0; d < 64; d++) {
            ulonglong2 q01 = *(const ulonglong2*)&Qs[d][ty * 8];
            ulonglong2 q23 = *(const ulonglong2*)&Qs[d][ty * 8 + 4];
            ulonglong2 kp  = *(const ulonglong2*)&Ks[d][tx * 4];
            fma2(sd[0][0], q01.x, kp.x); fma2(sd[0][1], q01.x, kp.y);
            fma2(sd[1][0], q01.y, kp.x); fma2(sd[1][1], q01.y, kp.y);
            fma2(sd[2][0], q23.x, kp.x); fma2(sd[2][1], q23.x, kp.y);
            fma2(sd[3][0], q23.y, kp.x); fma2(sd[3][1], q23.y, kp.y);
        }
        float S[4][4];
        #pragma unroll
        for (int i = 0; i < 4; i++) {
            float2 v0 = unpack2(sd[i][0]), v1 = unpack2(sd[i][1]);
            S[i][0] = v0.x; S[i][1] = v0.y; S[i][2] = v1.x; S[i][3] = v1.y;
        }

        if (tile < nt - 1) {
            #pragma unroll
            for (int i = 0; i < 4; i++) {
                float rmax = fmaxf(fmaxf(S[i][0], S[i][1]), fmaxf(S[i][2], S[i][3]));
                #pragma unroll
                for (int o = 8; o > 0; o >>= 1)
                    rmax = fmaxf(rmax, __shfl_xor_sync(0xffffffffu, rmax, o));
                float mnew = fmaxf(m[i], rmax);
                float sc = __expf(m[i] - mnew);
                float p[4], ps;
                p[0] = __expf(S[i][0] - mnew); p[1] = __expf(S[i][1] - mnew);
                p[2] = __expf(S[i][2] - mnew); p[3] = __expf(S[i][3] - mnew);
                ps = p[0] + p[1] + p[2] + p[3];
                #pragma unroll
                for (int o = 8; o > 0; o >>= 1)
                    ps += __shfl_xor_sync(0xffffffffu, ps, o);
                l[i] = l[i] * sc + ps;
                m[i] = mnew;
                u64 scd = dup2(sc);
                od[i][0] = mul2(od[i][0], scd);
                od[i][1] = mul2(od[i][1], scd);
                int qc = (ty * 4 + i) * 2;
                *(float2*)&Ps[tx * 4 + 0][qc] = make_float2(p[0], p[0]);
                *(float2*)&Ps[tx * 4 + 1][qc] = make_float2(p[1], p[1]);
                *(float2*)&Ps[tx * 4 + 2][qc] = make_float2(p[2], p[2]);
                *(float2*)&Ps[tx * 4 + 3][qc] = make_float2(p[3], p[3]);
            }
        } else {
            float4 tm4 = *(const float4*)&tmask[b * Tn + t0 + tx * 4];
            float tma[4] = {tm4.x, tm4.y, tm4.z, tm4.w};
            #pragma unroll
            for (int i = 0; i < 4; i++) {
                int qg = qb + ty * 4 + i;
                float4 qt4 = *(const float4*)&qtmask[((size_t)(b * Qn + qg)) * Tn + t0 + tx * 4];
                float qta[4] = {qt4.x, qt4.y, qt4.z, qt4.w};
                float rmax = -1e30f;
                bool act[4];
                #pragma unroll
                for (int j = 0; j < 4; j++) {
                    act[j] = (1.0f - fmaxf(tma[j], qta[j])) > 0.0f;
                    S[i][j] = act[j] ? S[i][j] : -1e30f;
                    rmax = fmaxf(rmax, S[i][j]);
                }
                #pragma unroll
                for (int o = 8; o > 0; o >>= 1)
                    rmax = fmaxf(rmax, __shfl_xor_sync(0xffffffffu, rmax, o));
                float mnew = fmaxf(m[i], rmax);
                float sc = __expf(m[i] - mnew);
                float p[4], ps = 0.0f;
                #pragma unroll
                for (int j = 0; j < 4; j++) {
                    p[j] = act[j] ? __expf(S[i][j] - mnew) : 0.0f;
                    ps += p[j];
                }
                #pragma unroll
                for (int o = 8; o > 0; o >>= 1)
                    ps += __shfl_xor_sync(0xffffffffu, ps, o);
                l[i] = l[i] * sc + ps;
                m[i] = mnew;
                u64 scd = dup2(sc);
                od[i][0] = mul2(od[i][0], scd);
                od[i][1] = mul2(od[i][1], scd);
                int qc = (ty * 4 + i) * 2;
                *(float2*)&Ps[tx * 4 + 0][qc] = make_float2(p[0], p[0]);
                *(float2*)&Ps[tx * 4 + 1][qc] = make_float2(p[1], p[1]);
                *(float2*)&Ps[tx * 4 + 2][qc] = make_float2(p[2], p[2]);
                *(float2*)&Ps[tx * 4 + 3][qc] = make_float2(p[3], p[3]);
            }
        }
        __syncthreads();

        #pragma unroll 8
        for (int t = 0; t < 64; t++) {
            ulonglong2 p01 = *(const ulonglong2*)&Ps[t][ty * 8];
            ulonglong2 p23 = *(const ulonglong2*)&Ps[t][ty * 8 + 4];
            ulonglong2 vp  = *(const ulonglong2*)&Vs[t * 64 + tx * 4];
            fma2(od[0][0], p01.x, vp.x); fma2(od[0][1], p01.x, vp.y);
            fma2(od[1][0], p01.y, vp.x); fma2(od[1][1], p01.y, vp.y);
            fma2(od[2][0], p23.x, vp.x); fma2(od[2][1], p23.x, vp.y);
            fma2(od[3][0], p23.y, vp.x); fma2(od[3][1], p23.y, vp.y);
        }
    }

    #pragma unroll
    for (int i = 0; i < 4; i++) {
        int qg = qb + ty * 4 + i;
        float inv = 1.0f / l[i];
        float2 v0 = unpack2(od[i][0]), v1 = unpack2(od[i][1]);
        float4 o = make_float4(v0.x * inv, v0.y * inv, v1.x * inv, v1.y * inv);
        *(float4*)&g_preF[((size_t)(b * Qn + qg)) * 1024 + h * 64 + tx * 4] = o;
        if (tx == 0) {
            g_m[bh * Qn + qg] = m[i];
            g_l[bh * Qn + qg] = l[i];
        }
    }
}

// ---------------- column sums pass 2 (R10, unchanged) ---------------------------
__global__ __launch_bounds__(256) void colsum_kernel(const float* __restrict__ tmask,
                                                     const float* __restrict__ qtmask) {
    __shared__ float ksh[32][64];
    __shared__ float qsh[64][65];
    __shared__ float msh[64], lsh[64], rsh[64];
    int b = blockIdx.z, h = blockIdx.y;
    int tb = blockIdx.x * 32;
    int tid = threadIdx.x, lane = tid & 31, warp = tid >> 5;

    const float* kbase = g_k + ((size_t)(b * Hn + h) * Tn + tb) * Kd;
    for (int e = tid * 4; e < 32 * 64; e += 1024)
        *(float4*)&((float*)ksh)[e] = *(const float4*)&kbase[e];

    float csum[4] = {0, 0, 0, 0};
    int hq = (b * Hn + h) * Qn;
    const float* qmat = g_q + (size_t)hq * Kd;
    int qstart = (tb / 64) * 64;

    for (int q0 = qstart; q0 < Qn; q0 += 64) {
        __syncthreads();
        for (int e = tid * 4; e < 64 * 64; e += 1024) {
            int qq = e >> 6, d = e & 63;
            float4 v = *(const float4*)&qmat[(size_t)q0 * 64 + e];
            qsh[qq][d + 0] = v.x; qsh[qq][d + 1] = v.y; qsh[qq][d + 2] = v.z; qsh[qq][d + 3] = v.w;
        }
        if (tid < 64) {
            msh[tid] = g_m[hq + q0 + tid];
            lsh[tid] = g_l[hq + q0 + tid];
            rsh[tid] = g_rowocc[b * Qn + q0 + tid];
        }
        __syncthreads();

        float s0[4] = {0, 0, 0, 0}, s1[4] = {0, 0, 0, 0};
        #pragma unroll 16
        for (int d = 0; d < 64; d++) {
            float qv0 = qsh[lane][d], qv1 = qsh[lane + 32][d];
            #pragma unroll
            for (int i = 0; i < 4; i++) {
                float kv = ksh[warp * 4 + i][d];
                s0[i] += kv * qv0;
                s1[i] += kv * qv1;
            }
        }
        if (q0 == qstart) {
            #pragma unroll
            for (int i = 0; i < 4; i++) {
                int t = tb + warp * 4 + i;
                float tmv = tmask[b * Tn + t];
                int qg0 = q0 + lane, qg1 = q0 + lane + 32;
                float occ0 = 1.0f - fmaxf(tmv, qtmask[(size_t)(b * Qn + qg0) * Tn + t]);
                float occ1 = 1.0f - fmaxf(tmv, qtmask[(size_t)(b * Qn + qg1) * Tn + t]);
                if (occ0 > 0.0f) csum[i] += __expf(s0[i] - msh[lane]) / lsh[lane] * rsh[lane];
                if (occ1 > 0.0f) csum[i] += __expf(s1[i] - msh[lane + 32]) / lsh[lane + 32] * rsh[lane + 32];
            }
        } else {
            #pragma unroll
            for (int i = 0; i < 4; i++) {
                csum[i] += __expf(s0[i] - msh[lane]) / lsh[lane] * rsh[lane]
                         + __expf(s1[i] - msh[lane + 32]) / lsh[lane + 32] * rsh[lane + 32];
            }
        }
    }
    #pragma unroll
    for (int i = 0; i < 4; i++) {
        float v = warpSum(csum[i]);
        if (lane == 0) atomicAdd(&g_colsum[b * Tn + tb + warp * 4 + i], v);
    }
}

// ---------------- entropy -------------------------------------------------------
__global__ __launch_bounds__(256) void entropy_kernel(float* __restrict__ eout) {
    int b = blockIdx.x, tid = threadIdx.x;
    int lane = tid & 31, warp = tid >> 5;
    __shared__ float sh0[8], sh1[8];
    float sm = 0.0f, sa = 0.0f;
    for (int t = tid; t < Tn; t += 256) {
        sm += g_colsum[b * Tn + t];
        sa += g_colact[b * Tn + t];
    }
    sm = warpSum(sm); sa = warpSum(sa);
    if (lane == 0) { sh0[warp] = sm; sh1[warp] = sa; }
    __syncthreads();
    float tsum = 0.0f, csum = 0.0f;
    #pragma unroll
    for (int w = 0; w < 8; w++) { tsum += sh0[w]; csum += sh1[w]; }
    __syncthreads();
    float ent = 0.0f;
    for (int t = tid; t < Tn; t += 256) {
        float p = g_colsum[b * Tn + t] / tsum;
        if (g_colact[b * Tn + t] > 0.0f && p > 0.0f) ent -= p * log2f(p);
    }
    ent = warpSum(ent);
    if (lane == 0) sh0[warp] = ent;
    __syncthreads();
    if (tid == 0) {
        float e = 0.0f;
        #pragma unroll
        for (int w = 0; w < 8; w++) e += sh0[w];
        eout[b] = e / log2f(csum);
    }
}

// ---------------- launch --------------------------------------------------------
extern "C" void kernel_launch(void* const* d_in, const int* in_sizes, int n_in,
                              void* d_out, int out_size) {
    const float* qinput  = (const float*)d_in[0];
    const float* kvinput = (const float*)d_in[1];
    const float* qmask   = (const float*)d_in[2];
    const float* tmask   = (const float*)d_in[3];
    const float* qtmask  = (const float*)d_in[4];
    const float* wq      = (const float*)d_in[5];
    const float* wk      = (const float*)d_in[6];
    const float* wv      = (const float*)d_in[7];
    const float* wo      = (const float*)d_in[8];
    float* out  = (float*)d_out;
    float* eout = out + (out_size - Bq);

    const int ATTN_SMEM = (64 * 132 + 64 * 68 + 64 * 64 + 64 * 132) * 4;  // 101376 B
    const int HG_SMEM = 2 * 40960;                                        // 81920 B
    cudaFuncSetAttribute(attn3_kernel, cudaFuncAttributeMaxDynamicSharedMemorySize, ATTN_SMEM);
    cudaFuncSetAttribute(hgemm_kernel, cudaFuncAttributeMaxDynamicSharedMemorySize, HG_SMEM);

    init_kernel<<<(Bq * Tn + 255) / 256, 256>>>();
    rowocc_kernel<<<(Bq * Qn) / 8, 256>>>(tmask, qtmask);
    colact_kernel<<<dim3(Tn / 256, Bq), 256>>>(tmask, qtmask);

    convA2_kernel<<<4096, 256>>>(qinput, 0);
    convA2_kernel<<<4096, 256>>>(kvinput, 1);
    convW2_kernel<<<dim3(16, 16, 3), 256>>>(wq, wk, wv);
    convWo2_kernel<<<dim3(16, 16), 256>>>(wo);

    for (int z = 0; z < 3; z++)
        hgemm_kernel<<<dim3(32, 8), 256, HG_SMEM>>>(0, nullptr, nullptr, z);

    attn3_kernel<<<dim3(Qn / 64, Hn, Bq), 256, ATTN_SMEM>>>(tmask, qtmask);
    colsum_kernel<<<dim3(Tn / 32, Hn, Bq), 256>>>(tmask, qtmask);
    entropy_kernel<<<Bq, 256>>>(eout);

    convA2_kernel<<<4096, 256>>>(nullptr, 2);
    hgemm_kernel<<<dim3(32, 8), 256, HG_SMEM>>>(1, qmask, out, 0);
}

// round 12
// speedup vs baseline: 2.0406x; 1.3868x over previous
#include <cuda_runtime.h>
#include <cuda_bf16.h>
#include <math.h>
#include <stdint.h>

#define Bq 4
#define Qn 1024
#define Tn 1024
#define Hn 16
#define Mn 1024
#define Kd 64
#define Vd 64

// ---------------- scratch (static device globals; no runtime alloc) ----------
__device__ float g_q[Bq*Hn*Qn*Kd];
__device__ float g_k[Bq*Hn*Tn*Kd];
__device__ float g_v[Bq*Hn*Tn*Vd];
__device__ float g_preF[Bq*Qn*Hn*Vd];  // [b*1024+q][h*64+d]
__device__ float g_m[Bq*Hn*Qn];
__device__ float g_l[Bq*Hn*Qn];
__device__ float g_rowocc[Bq*Qn];
__device__ float g_colact[Bq*Tn];
__device__ float g_colsum[Bq*Tn];

// bf16 hi/lo operands for GEMMs (row-major, k-contiguous)
__device__ __align__(16) __nv_bfloat16 cAq_h[4096*1024],  cAq_l[4096*1024];
__device__ __align__(16) __nv_bfloat16 cAkv_h[4096*1024], cAkv_l[4096*1024];
__device__ __align__(16) __nv_bfloat16 cApre_h[4096*1024],cApre_l[4096*1024];
__device__ __align__(16) __nv_bfloat16 cBq_h[1024*1024],  cBq_l[1024*1024];
__device__ __align__(16) __nv_bfloat16 cBk_h[1024*1024],  cBk_l[1024*1024];
__device__ __align__(16) __nv_bfloat16 cBv_h[1024*1024],  cBv_l[1024*1024];
__device__ __align__(16) __nv_bfloat16 cBo_h[1024*1024],  cBo_l[1024*1024];

// bf16 hi/lo for attention
__device__ __align__(16) __nv_bfloat16 g_qh[Bq*Hn*Qn*Kd], g_ql[Bq*Hn*Qn*Kd];
__device__ __align__(16) __nv_bfloat16 g_kh[Bq*Hn*Tn*Kd], g_kl[Bq*Hn*Tn*Kd];
__device__ __align__(16) __nv_bfloat16 g_vTh[Bq*Hn*Kd*Tn], g_vTl[Bq*Hn*Kd*Tn]; // [bh][d][t]

// ---------------- helpers ------------------------------------------------------
__device__ __forceinline__ uint32_t smem_u32(const void* p) {
    uint32_t a;
    asm("{ .reg .u64 t; cvta.to.shared.u64 t, %1; cvt.u32.u64 %0, t; }" : "=r"(a) : "l"(p));
    return a;
}
__device__ __forceinline__ void split2(float x, unsigned short &h, unsigned short &l) {
    __nv_bfloat16 hb = __float2bfloat16(x);
    float r = x - __bfloat162float(hb);
    __nv_bfloat16 lb = __float2bfloat16(r);
    h = __bfloat16_as_ushort(hb);
    l = __bfloat16_as_ushort(lb);
}
__device__ __forceinline__ float warpSum(float v) {
    #pragma unroll
    for (int o = 16; o > 0; o >>= 1) v += __shfl_xor_sync(0xffffffffu, v, o);
    return v;
}
#define LDX4(r0, r1, r2, r3, addr) \
    asm volatile("ldmatrix.sync.aligned.m8n8.x4.shared.b16 {%0,%1,%2,%3}, [%4];" \
        : "=r"(r0), "=r"(r1), "=r"(r2), "=r"(r3) : "r"(addr))
#define MMA16816(d, a, b) \
    asm volatile("mma.sync.aligned.m16n8k16.row.col.f32.bf16.bf16.f32 " \
        "{%0,%1,%2,%3}, {%4,%5,%6,%7}, {%8,%9}, {%0,%1,%2,%3};" \
        : "+f"((d)[0]), "+f"((d)[1]), "+f"((d)[2]), "+f"((d)[3]) \
        : "r"((a)[0]), "r"((a)[1]), "r"((a)[2]), "r"((a)[3]), "r"((b)[0]), "r"((b)[1]))

// ---------------- small kernels -------------------------------------------------
__global__ void init_kernel() {
    int i = blockIdx.x * blockDim.x + threadIdx.x;
    if (i < Bq * Tn) g_colsum[i] = 0.0f;
}

__global__ __launch_bounds__(256) void rowocc_kernel(const float* __restrict__ tmask,
                                                     const float* __restrict__ qtmask) {
    int warp = threadIdx.x >> 5, lane = threadIdx.x & 31;
    int row = blockIdx.x * 8 + warp;
    if (row >= Bq * Qn) return;
    int b = row / Qn;
    float acc = 0.0f;
    const float* qt = qtmask + (size_t)row * Tn;
    const float* tm = tmask + (size_t)b * Tn;
    for (int t = lane; t < Tn; t += 32)
        acc += 1.0f - fmaxf(tm[t], qt[t]);
    acc = warpSum(acc);
    if (lane == 0) g_rowocc[row] = acc;
}

__global__ __launch_bounds__(256) void colact_kernel(const float* __restrict__ tmask,
                                                     const float* __restrict__ qtmask) {
    int b = blockIdx.y;
    int t = blockIdx.x * blockDim.x + threadIdx.x;
    if (t >= Tn) return;
    float tmv = tmask[b * Tn + t];
    float mx = -1e30f;
    for (int q = 0; q < Qn; q++) {
        float occ = 1.0f - fmaxf(tmv, qtmask[((size_t)(b * Qn + q)) * Tn + t]);
        mx = fmaxf(mx, occ);
    }
    g_colact[b * Tn + t] = mx;
}

// ---------------- conversions ---------------------------------------------------
__global__ __launch_bounds__(256) void convA2_kernel(const float* __restrict__ srcp, int sel) {
    const float* src = srcp;
    __nv_bfloat16 *dh, *dl;
    if (sel == 0)      { dh = cAq_h;  dl = cAq_l;  }
    else if (sel == 1) { dh = cAkv_h; dl = cAkv_l; }
    else               { src = g_preF; dh = cApre_h; dl = cApre_l; }
    size_t i4 = ((size_t)blockIdx.x * 256 + threadIdx.x) * 4;
    float4 v = *(const float4*)&src[i4];
    unsigned short h0, l0, h1, l1, h2, l2, h3, l3;
    split2(v.x, h0, l0); split2(v.y, h1, l1); split2(v.z, h2, l2); split2(v.w, h3, l3);
    uint2 ph = make_uint2(((unsigned)h1 << 16) | h0, ((unsigned)h3 << 16) | h2);
    uint2 pl = make_uint2(((unsigned)l1 << 16) | l0, ((unsigned)l3 << 16) | l2);
    *(uint2*)&dh[i4] = ph;
    *(uint2*)&dl[i4] = pl;
}

// g_q/g_k f32 -> bf16 hi/lo same layout
__global__ __launch_bounds__(256) void convQK_kernel(int sel) {
    const float* src = sel ? g_k : g_q;
    __nv_bfloat16* dh = sel ? g_kh : g_qh;
    __nv_bfloat16* dl = sel ? g_kl : g_ql;
    size_t i4 = ((size_t)blockIdx.x * 256 + threadIdx.x) * 4;
    float4 v = *(const float4*)&src[i4];
    unsigned short h0, l0, h1, l1, h2, l2, h3, l3;
    split2(v.x, h0, l0); split2(v.y, h1, l1); split2(v.z, h2, l2); split2(v.w, h3, l3);
    *(uint2*)&dh[i4] = make_uint2(((unsigned)h1 << 16) | h0, ((unsigned)h3 << 16) | h2);
    *(uint2*)&dl[i4] = make_uint2(((unsigned)l1 << 16) | l0, ((unsigned)l3 << 16) | l2);
}

// g_v [bh][t][d] f32 -> g_vT [bh][d][t] bf16 hi/lo
__global__ __launch_bounds__(256) void convVT_kernel() {
    __shared__ float st[64][65];
    int bh = blockIdx.y, t0 = blockIdx.x * 64;
    int tid = threadIdx.x;
    #pragma unroll
    for (int it = 0; it < 4; it++) {
        int e = (it * 256 + tid) * 4;
        int t = e >> 6, d = e & 63;
        float4 v = *(const float4*)&g_v[((size_t)bh * Tn + t0 + t) * 64 + d];
        st[t][d] = v.x; st[t][d + 1] = v.y; st[t][d + 2] = v.z; st[t][d + 3] = v.w;
    }
    __syncthreads();
    #pragma unroll
    for (int it = 0; it < 8; it++) {
        int u = it * 256 + tid;
        int d = u >> 5, tp = (u & 31) * 2;
        unsigned short h0, l0, h1, l1;
        split2(st[tp][d], h0, l0);
        split2(st[tp + 1][d], h1, l1);
        size_t idx = ((size_t)bh * 64 + d) * 1024 + t0 + tp;
        *(unsigned*)&g_vTh[idx] = ((unsigned)h1 << 16) | h0;
        *(unsigned*)&g_vTl[idx] = ((unsigned)l1 << 16) | l0;
    }
}

// wq/wk/wv [h][m][d] -> Bt[n=h*64+d][k=m]; kscale folded into wq
__global__ __launch_bounds__(256) void convW2_kernel(const float* __restrict__ wq_,
                                                     const float* __restrict__ wk_,
                                                     const float* __restrict__ wv_) {
    __shared__ float st[64][65];
    int z = blockIdx.z, h = blockIdx.x, mc = blockIdx.y;
    const float* W = (z == 0) ? wq_ : (z == 1) ? wk_ : wv_;
    __nv_bfloat16* dh = (z == 0) ? cBq_h : (z == 1) ? cBk_h : cBv_h;
    __nv_bfloat16* dl = (z == 0) ? cBq_l : (z == 1) ? cBk_l : cBv_l;
    float sc = (z == 0) ? 0.125f : 1.0f;
    int tid = threadIdx.x;
    #pragma unroll
    for (int i = 0; i < 4; i++) {
        int e = tid + i * 256;
        int mm = e >> 4, d4 = (e & 15) * 4;
        float4 v = *(const float4*)&W[(size_t)h * 65536 + (size_t)(mc * 64 + mm) * 64 + d4];
        st[mm][d4] = v.x * sc; st[mm][d4 + 1] = v.y * sc;
        st[mm][d4 + 2] = v.z * sc; st[mm][d4 + 3] = v.w * sc;
    }
    __syncthreads();
    int d = tid >> 2, mg = (tid & 3) * 16;
    unsigned ph[8], pl[8];
    #pragma unroll
    for (int j = 0; j < 8; j++) {
        unsigned short ha, la, hb, lb;
        split2(st[mg + 2 * j][d], ha, la);
        split2(st[mg + 2 * j + 1][d], hb, lb);
        ph[j] = ((unsigned)hb << 16) | ha;
        pl[j] = ((unsigned)lb << 16) | la;
    }
    size_t base = (size_t)(h * 64 + d) * 1024 + mc * 64 + mg;
    *(uint4*)&dh[base]     = make_uint4(ph[0], ph[1], ph[2], ph[3]);
    *(uint4*)&dh[base + 8] = make_uint4(ph[4], ph[5], ph[6], ph[7]);
    *(uint4*)&dl[base]     = make_uint4(pl[0], pl[1], pl[2], pl[3]);
    *(uint4*)&dl[base + 8] = make_uint4(pl[4], pl[5], pl[6], pl[7]);
}

__global__ __launch_bounds__(256) void convWo2_kernel(const float* __restrict__ wo) {
    __shared__ float st[64][65];
    int h = blockIdx.x, mc = blockIdx.y;
    int tid = threadIdx.x;
    #pragma unroll
    for (int i = 0; i < 4; i++) {
        int e = tid + i * 256;
        int v = e >> 4, m4 = (e & 15) * 4;
        float4 x = *(const float4*)&wo[(size_t)(h * 64 + v) * 1024 + mc * 64 + m4];
        st[v][m4] = x.x; st[v][m4 + 1] = x.y; st[v][m4 + 2] = x.z; st[v][m4 + 3] = x.w;
    }
    __syncthreads();
    int mm = tid >> 2, vg = (tid & 3) * 16;
    unsigned ph[8], pl[8];
    #pragma unroll
    for (int j = 0; j < 8; j++) {
        unsigned short ha, la, hb, lb;
        split2(st[vg + 2 * j][mm], ha, la);
        split2(st[vg + 2 * j + 1][mm], hb, lb);
        ph[j] = ((unsigned)hb << 16) | ha;
        pl[j] = ((unsigned)lb << 16) | la;
    }
    size_t base = (size_t)(mc * 64 + mm) * 1024 + h * 64 + vg;
    *(uint4*)&cBo_h[base]     = make_uint4(ph[0], ph[1], ph[2], ph[3]);
    *(uint4*)&cBo_h[base + 8] = make_uint4(ph[4], ph[5], ph[6], ph[7]);
    *(uint4*)&cBo_l[base]     = make_uint4(pl[0], pl[1], pl[2], pl[3]);
    *(uint4*)&cBo_l[base + 8] = make_uint4(pl[4], pl[5], pl[6], pl[7]);
}

// ---------------- HMMA GEMM (R11, unchanged) ------------------------------------
__device__ __forceinline__ void hg_prefetch(uint32_t sbuf,
        const __nv_bfloat16* Ah, const __nv_bfloat16* Al,
        const __nv_bfloat16* Bh, const __nv_bfloat16* Bl,
        int rowBase, int cn, int k0, int tid) {
    #pragma unroll
    for (int j = 0; j < 8; j++) {
        int lin = j * 256 + tid;
        int arr = lin >> 9, within = lin & 511;
        int row = within >> 2, seg = within & 3;
        const __nv_bfloat16* g;
        if (arr == 0)      g = Ah + (size_t)(rowBase + row) * 1024;
        else if (arr == 1) g = Al + (size_t)(rowBase + row) * 1024;
        else if (arr == 2) g = Bh + (size_t)(cn + row) * 1024;
        else               g = Bl + (size_t)(cn + row) * 1024;
        g += k0 + seg * 8;
        uint32_t s = sbuf + arr * 10240 + row * 80 + seg * 16;
        asm volatile("cp.async.cg.shared.global [%0], [%1], 16;" :: "r"(s), "l"(g));
    }
}

__global__ __launch_bounds__(256) void hgemm_kernel(int mode,
        const float* __restrict__ qmask, float* __restrict__ outp, int z) {
    extern __shared__ char sm[];
    uint32_t sb = smem_u32(sm);
    int tid = threadIdx.x, lane = tid & 31, wid = tid >> 5;
    int warp_m = wid & 1, warp_n = wid >> 1;

    const __nv_bfloat16 *Ah, *Al, *Bh, *Bl;
    float* C;
    if (mode == 0) {
        Ah = (z == 0) ? cAq_h : cAkv_h;
        Al = (z == 0) ? cAq_l : cAkv_l;
        Bh = (z == 0) ? cBq_h : (z == 1) ? cBk_h : cBv_h;
        Bl = (z == 0) ? cBq_l : (z == 1) ? cBk_l : cBv_l;
        C  = (z == 0) ? g_q : (z == 1) ? g_k : g_v;
    } else {
        Ah = cApre_h; Al = cApre_l; Bh = cBo_h; Bl = cBo_l; C = outp;
    }
    int rowBase = blockIdx.x * 128;
    int cn = blockIdx.y * 128;

    float acc[4][4][4];
    #pragma unroll
    for (int i = 0; i < 4; i++)
        #pragma unroll
        for (int j = 0; j < 4; j++)
            #pragma unroll
            for (int r = 0; r < 4; r++) acc[i][j][r] = 0.0f;

    int laneRow = lane & 15, laneK = lane >> 4;
    uint32_t aOff = (uint32_t)((warp_m * 64 + laneRow) * 80 + laneK * 16);
    uint32_t bOff = (uint32_t)(20480 + (warp_n * 32 + laneRow) * 80 + laneK * 16);

    hg_prefetch(sb, Ah, Al, Bh, Bl, rowBase, cn, 0, tid);
    asm volatile("cp.async.commit_group;");

    for (int c = 0; c < 32; c++) {
        uint32_t sbuf = sb + (c & 1) * 40960;
        if (c < 31) {
            hg_prefetch(sb + ((c + 1) & 1) * 40960, Ah, Al, Bh, Bl, rowBase, cn, (c + 1) * 32, tid);
            asm volatile("cp.async.commit_group;");
            asm volatile("cp.async.wait_group 1;");
        } else {
            asm volatile("cp.async.wait_group 0;");
        }
        __syncthreads();

        #pragma unroll
        for (int ks = 0; ks < 2; ks++) {
            uint32_t kOff = ks * 32;
            unsigned bh[4][2], bl[4][2];
            {
                unsigned r0, r1, r2, r3;
                LDX4(r0, r1, r2, r3, sbuf + bOff + kOff);
                bh[0][0] = r0; bh[0][1] = r2; bh[1][0] = r1; bh[1][1] = r3;
                LDX4(r0, r1, r2, r3, sbuf + bOff + kOff + 1280);
                bh[2][0] = r0; bh[2][1] = r2; bh[3][0] = r1; bh[3][1] = r3;
                LDX4(r0, r1, r2, r3, sbuf + bOff + kOff + 10240);
                bl[0][0] = r0; bl[0][1] = r2; bl[1][0] = r1; bl[1][1] = r3;
                LDX4(r0, r1, r2, r3, sbuf + bOff + kOff + 11520);
                bl[2][0] = r0; bl[2][1] = r2; bl[3][0] = r1; bl[3][1] = r3;
            }
            #pragma unroll
            for (int mt = 0; mt < 4; mt++) {
                unsigned ah[4], al4[4];
                uint32_t aAddr = sbuf + aOff + kOff + mt * 1280;
                LDX4(ah[0], ah[1], ah[2], ah[3], aAddr);
                LDX4(al4[0], al4[1], al4[2], al4[3], aAddr + 10240);
                #pragma unroll
                for (int nt = 0; nt < 4; nt++) {
                    MMA16816(acc[mt][nt], ah, bh[nt]);
                    MMA16816(acc[mt][nt], ah, bl[nt]);
                    MMA16816(acc[mt][nt], al4, bh[nt]);
                }
            }
        }
        __syncthreads();
    }

    int g = lane >> 2, tc = (lane & 3) * 2;
    #pragma unroll
    for (int mt = 0; mt < 4; mt++) {
        #pragma unroll
        for (int nt = 0; nt < 4; nt++) {
            int r0 = rowBase + warp_m * 64 + mt * 16 + g;
            int cc = cn + warp_n * 32 + nt * 8 + tc;
            if (mode == 0) {
                int h = cc >> 6, d = cc & 63;
                int b0 = r0 >> 10, q0 = r0 & 1023;
                float* d0 = &C[(((size_t)(b0 * Hn + h)) * Qn + q0) * Kd + d];
                *(float2*)d0 = make_float2(acc[mt][nt][0], acc[mt][nt][1]);
                int r1 = r0 + 8;
                int b1 = r1 >> 10, q1 = r1 & 1023;
                float* d1 = &C[(((size_t)(b1 * Hn + h)) * Qn + q1) * Kd + d];
                *(float2*)d1 = make_float2(acc[mt][nt][2], acc[mt][nt][3]);
            } else {
                float w0 = 1.0f - qmask[r0];
                float w1 = 1.0f - qmask[r0 + 8];
                *(float2*)&C[(size_t)r0 * 1024 + cc] =
                    make_float2(acc[mt][nt][0] * w0, acc[mt][nt][1] * w0);
                *(float2*)&C[(size_t)(r0 + 8) * 1024 + cc] =
                    make_float2(acc[mt][nt][2] * w1, acc[mt][nt][3] * w1);
            }
        }
    }
}

// ---------------- flash attention via HMMA --------------------------------------
// block: 128 q x (tiles of 64 t); 8 warps, warp w owns q rows [qb+16w, qb+16w+16).
// smem byte offsets (row stride 144B = 72 bf16):
#define QH_OFF 0
#define QL_OFF 18432
#define KH_OFF 36864
#define KL_OFF 46080
#define VTH_OFF 55296
#define VTL_OFF 64512
#define ATTN4_SMEM 73728

__global__ __launch_bounds__(256) void attn4_kernel(const float* __restrict__ tmask,
                                                    const float* __restrict__ qtmask) {
    extern __shared__ char sm4[];
    uint32_t sb = smem_u32(sm4);
    int b = blockIdx.z, h = blockIdx.y;
    int qb = (gridDim.x - 1 - blockIdx.x) * 128;   // longest first
    int bh = b * Hn + h;
    int tid = threadIdx.x, lane = tid & 31, w = tid >> 5;
    int laneRow = lane & 15, laneK = lane >> 4;
    int g = lane >> 2, qc = lane & 3;

    // load Q hi/lo (128 rows x 64 d)
    #pragma unroll
    for (int j = 0; j < 8; j++) {
        int lin = j * 256 + tid;
        int arr = lin >> 10, row = (lin >> 3) & 127, seg = lin & 7;
        const __nv_bfloat16* src = (arr ? g_ql : g_qh) + ((size_t)bh * Qn + qb + row) * 64 + seg * 8;
        uint32_t dst = sb + (arr ? QL_OFF : QH_OFF) + row * 144 + seg * 16;
        asm volatile("cp.async.cg.shared.global [%0], [%1], 16;" :: "r"(dst), "l"(src));
    }
    asm volatile("cp.async.commit_group;");

    float accO[8][4];
    #pragma unroll
    for (int i = 0; i < 8; i++)
        #pragma unroll
        for (int r = 0; r < 4; r++) accO[i][r] = 0.0f;
    float mrow[2] = {-1e30f, -1e30f}, lrow[2] = {0.0f, 0.0f};

    int qmin = qb + 16 * w, qmax = qmin + 15;
    int ntls = qb / 64 + 2;

    for (int tile = 0; tile < ntls; tile++) {
        int t0 = tile * 64;
        __syncthreads();   // previous tile's compute done before overwrite
        #pragma unroll
        for (int j = 0; j < 8; j++) {
            int lin = j * 256 + tid;
            int arr = lin >> 9, within = lin & 511;
            int row = within >> 3, seg = within & 7;
            const __nv_bfloat16* src;
            uint32_t off;
            if (arr == 0)      { src = g_kh + ((size_t)bh * Tn + t0 + row) * 64 + seg * 8; off = KH_OFF; }
            else if (arr == 1) { src = g_kl + ((size_t)bh * Tn + t0 + row) * 64 + seg * 8; off = KL_OFF; }
            else if (arr == 2) { src = g_vTh + ((size_t)bh * 64 + row) * 1024 + t0 + seg * 8; off = VTH_OFF; }
            else               { src = g_vTl + ((size_t)bh * 64 + row) * 1024 + t0 + seg * 8; off = VTL_OFF; }
            uint32_t dst = sb + off + row * 144 + seg * 16;
            asm volatile("cp.async.cg.shared.global [%0], [%1], 16;" :: "r"(dst), "l"(src));
        }
        asm volatile("cp.async.commit_group;");
        asm volatile("cp.async.wait_group 0;");
        __syncthreads();

        if (t0 > qmax) continue;   // fully masked for this warp (sync already done)

        // ---- S = Q K^T (hi/lo split) ----
        float accS[8][4];
        #pragma unroll
        for (int i = 0; i < 8; i++)
            #pragma unroll
            for (int r = 0; r < 4; r++) accS[i][r] = 0.0f;

        #pragma unroll
        for (int ks = 0; ks < 4; ks++) {
            uint32_t kOff = ks * 32;
            unsigned ah[4], al[4];
            uint32_t aAddr = sb + (16 * w + laneRow) * 144 + kOff + laneK * 16;
            LDX4(ah[0], ah[1], ah[2], ah[3], aAddr + QH_OFF);
            LDX4(al[0], al[1], al[2], al[3], aAddr + QL_OFF);
            unsigned kh2[8][2], kl2[8][2];
            #pragma unroll
            for (int p = 0; p < 4; p++) {
                unsigned r0, r1, r2, r3;
                uint32_t bAddr = sb + (p * 16 + laneRow) * 144 + kOff + laneK * 16;
                LDX4(r0, r1, r2, r3, bAddr + KH_OFF);
                kh2[2*p][0] = r0; kh2[2*p+1][0] = r1; kh2[2*p][1] = r2; kh2[2*p+1][1] = r3;
                LDX4(r0, r1, r2, r3, bAddr + KL_OFF);
                kl2[2*p][0] = r0; kl2[2*p+1][0] = r1; kl2[2*p][1] = r2; kl2[2*p+1][1] = r3;
            }
            #pragma unroll
            for (int nt = 0; nt < 8; nt++) {
                MMA16816(accS[nt], ah, kh2[nt]);
                MMA16816(accS[nt], ah, kl2[nt]);
                MMA16816(accS[nt], al, kh2[nt]);
            }
        }

        bool full = (t0 + 63 <= qmin);
        if (!full) {
            float tmv[8][2];
            #pragma unroll
            for (int nt = 0; nt < 8; nt++) {
                tmv[nt][0] = tmask[b * Tn + t0 + nt * 8 + qc * 2];
                tmv[nt][1] = tmask[b * Tn + t0 + nt * 8 + qc * 2 + 1];
            }
            #pragma unroll
            for (int rr = 0; rr < 2; rr++) {
                int q = qmin + g + rr * 8;
                const float* qtrow = qtmask + ((size_t)(b * Qn + q)) * Tn;
                #pragma unroll
                for (int nt = 0; nt < 8; nt++) {
                    #pragma unroll
                    for (int c = 0; c < 2; c++) {
                        int t = t0 + nt * 8 + qc * 2 + c;
                        if (!((1.0f - fmaxf(tmv[nt][c], qtrow[t])) > 0.0f))
                            accS[nt][rr * 2 + c] = -1e30f;
                    }
                }
            }
        }

        // ---- online softmax (rows in lane-quads) ----
        #pragma unroll
        for (int rr = 0; rr < 2; rr++) {
            float rmax = -1e30f;
            #pragma unroll
            for (int nt = 0; nt < 8; nt++)
                rmax = fmaxf(rmax, fmaxf(accS[nt][rr * 2], accS[nt][rr * 2 + 1]));
            rmax = fmaxf(rmax, __shfl_xor_sync(0xffffffffu, rmax, 1));
            rmax = fmaxf(rmax, __shfl_xor_sync(0xffffffffu, rmax, 2));
            float mnew = fmaxf(mrow[rr], rmax);
            float sc = __expf(mrow[rr] - mnew);
            float ps = 0.0f;
            #pragma unroll
            for (int nt = 0; nt < 8; nt++) {
                float p0 = __expf(accS[nt][rr * 2] - mnew);
                float p1 = __expf(accS[nt][rr * 2 + 1] - mnew);
                accS[nt][rr * 2] = p0; accS[nt][rr * 2 + 1] = p1;
                ps += p0 + p1;
            }
            ps += __shfl_xor_sync(0xffffffffu, ps, 1);
            ps += __shfl_xor_sync(0xffffffffu, ps, 2);
            lrow[rr] = lrow[rr] * sc + ps;
            mrow[rr] = mnew;
            #pragma unroll
            for (int dt = 0; dt < 8; dt++) {
                accO[dt][rr * 2] *= sc;
                accO[dt][rr * 2 + 1] *= sc;
            }
        }

        // ---- O += P V (P hi/lo from registers, V hi/lo from smem) ----
        #pragma unroll
        for (int kt = 0; kt < 4; kt++) {
            unsigned pah[4], pal[4];
            #pragma unroll
            for (int fi = 0; fi < 4; fi++) {
                int nt = 2 * kt + (fi >> 1);
                int base = (fi & 1) * 2;
                unsigned short ha, la, hb2, lb2;
                split2(accS[nt][base], ha, la);
                split2(accS[nt][base + 1], hb2, lb2);
                pah[fi] = ((unsigned)hb2 << 16) | ha;
                pal[fi] = ((unsigned)lb2 << 16) | la;
            }
            unsigned vh2[8][2], vl2[8][2];
            #pragma unroll
            for (int p = 0; p < 4; p++) {
                unsigned r0, r1, r2, r3;
                uint32_t bAddr = sb + (p * 16 + laneRow) * 144 + kt * 32 + laneK * 16;
                LDX4(r0, r1, r2, r3, bAddr + VTH_OFF);
                vh2[2*p][0] = r0; vh2[2*p+1][0] = r1; vh2[2*p][1] = r2; vh2[2*p+1][1] = r3;
                LDX4(r0, r1, r2, r3, bAddr + VTL_OFF);
                vl2[2*p][0] = r0; vl2[2*p+1][0] = r1; vl2[2*p][1] = r2; vl2[2*p+1][1] = r3;
            }
            #pragma unroll
            for (int dt = 0; dt < 8; dt++) {
                MMA16816(accO[dt], pah, vh2[dt]);
                MMA16816(accO[dt], pah, vl2[dt]);
                MMA16816(accO[dt], pal, vh2[dt]);
            }
        }
    }

    // epilogue
    #pragma unroll
    for (int rr = 0; rr < 2; rr++) {
        int q = qmin + g + rr * 8;
        float inv = 1.0f / lrow[rr];
        #pragma unroll
        for (int dt = 0; dt < 8; dt++) {
            int d = dt * 8 + qc * 2;
            *(float2*)&g_preF[((size_t)(b * Qn + q)) * 1024 + h * 64 + d] =
                make_float2(accO[dt][rr * 2] * inv, accO[dt][rr * 2 + 1] * inv);
        }
        if (qc == 0) {
            g_m[bh * Qn + q] = mrow[rr];
            g_l[bh * Qn + q] = lrow[rr];
        }
    }
}

// ---------------- column sums pass 2 (unchanged) --------------------------------
__global__ __launch_bounds__(256) void colsum_kernel(const float* __restrict__ tmask,
                                                     const float* __restrict__ qtmask) {
    __shared__ float ksh[32][64];
    __shared__ float qsh[64][65];
    __shared__ float msh[64], lsh[64], rsh[64];
    int b = blockIdx.z, h = blockIdx.y;
    int tb = blockIdx.x * 32;
    int tid = threadIdx.x, lane = tid & 31, warp = tid >> 5;

    const float* kbase = g_k + ((size_t)(b * Hn + h) * Tn + tb) * Kd;
    for (int e = tid * 4; e < 32 * 64; e += 1024)
        *(float4*)&((float*)ksh)[e] = *(const float4*)&kbase[e];

    float csum[4] = {0, 0, 0, 0};
    int hq = (b * Hn + h) * Qn;
    const float* qmat = g_q + (size_t)hq * Kd;
    int qstart = (tb / 64) * 64;

    for (int q0 = qstart; q0 < Qn; q0 += 64) {
        __syncthreads();
        for (int e = tid * 4; e < 64 * 64; e += 1024) {
            int qq = e >> 6, d = e & 63;
            float4 v = *(const float4*)&qmat[(size_t)q0 * 64 + e];
            qsh[qq][d + 0] = v.x; qsh[qq][d + 1] = v.y; qsh[qq][d + 2] = v.z; qsh[qq][d + 3] = v.w;
        }
        if (tid < 64) {
            msh[tid] = g_m[hq + q0 + tid];
            lsh[tid] = g_l[hq + q0 + tid];
            rsh[tid] = g_rowocc[b * Qn + q0 + tid];
        }
        __syncthreads();

        float s0[4] = {0, 0, 0, 0}, s1[4] = {0, 0, 0, 0};
        #pragma unroll 16
        for (int d = 0; d < 64; d++) {
            float qv0 = qsh[lane][d], qv1 = qsh[lane + 32][d];
            #pragma unroll
            for (int i = 0; i < 4; i++) {
                float kv = ksh[warp * 4 + i][d];
                s0[i] += kv * qv0;
                s1[i] += kv * qv1;
            }
        }
        if (q0 == qstart) {
            #pragma unroll
            for (int i = 0; i < 4; i++) {
                int t = tb + warp * 4 + i;
                float tmv = tmask[b * Tn + t];
                int qg0 = q0 + lane, qg1 = q0 + lane + 32;
                float occ0 = 1.0f - fmaxf(tmv, qtmask[(size_t)(b * Qn + qg0) * Tn + t]);
                float occ1 = 1.0f - fmaxf(tmv, qtmask[(size_t)(b * Qn + qg1) * Tn + t]);
                if (occ0 > 0.0f) csum[i] += __expf(s0[i] - msh[lane]) / lsh[lane] * rsh[lane];
                if (occ1 > 0.0f) csum[i] += __expf(s1[i] - msh[lane + 32]) / lsh[lane + 32] * rsh[lane + 32];
            }
        } else {
            #pragma unroll
            for (int i = 0; i < 4; i++) {
                csum[i] += __expf(s0[i] - msh[lane]) / lsh[lane] * rsh[lane]
                         + __expf(s1[i] - msh[lane + 32]) / lsh[lane + 32] * rsh[lane + 32];
            }
        }
    }
    #pragma unroll
    for (int i = 0; i < 4; i++) {
        float v = warpSum(csum[i]);
        if (lane == 0) atomicAdd(&g_colsum[b * Tn + tb + warp * 4 + i], v);
    }
}

// ---------------- entropy -------------------------------------------------------
__global__ __launch_bounds__(256) void entropy_kernel(float* __restrict__ eout) {
    int b = blockIdx.x, tid = threadIdx.x;
    int lane = tid & 31, warp = tid >> 5;
    __shared__ float sh0[8], sh1[8];
    float sm = 0.0f, sa = 0.0f;
    for (int t = tid; t < Tn; t += 256) {
        sm += g_colsum[b * Tn + t];
        sa += g_colact[b * Tn + t];
    }
    sm = warpSum(sm); sa = warpSum(sa);
    if (lane == 0) { sh0[warp] = sm; sh1[warp] = sa; }
    __syncthreads();
    float tsum = 0.0f, csum = 0.0f;
    #pragma unroll
    for (int w = 0; w < 8; w++) { tsum += sh0[w]; csum += sh1[w]; }
    __syncthreads();
    float ent = 0.0f;
    for (int t = tid; t < Tn; t += 256) {
        float p = g_colsum[b * Tn + t] / tsum;
        if (g_colact[b * Tn + t] > 0.0f && p > 0.0f) ent -= p * log2f(p);
    }
    ent = warpSum(ent);
    if (lane == 0) sh0[warp] = ent;
    __syncthreads();
    if (tid == 0) {
        float e = 0.0f;
        #pragma unroll
        for (int w = 0; w < 8; w++) e += sh0[w];
        eout[b] = e / log2f(csum);
    }
}

// ---------------- launch --------------------------------------------------------
extern "C" void kernel_launch(void* const* d_in, const int* in_sizes, int n_in,
                              void* d_out, int out_size) {
    const float* qinput  = (const float*)d_in[0];
    const float* kvinput = (const float*)d_in[1];
    const float* qmask   = (const float*)d_in[2];
    const float* tmask   = (const float*)d_in[3];
    const float* qtmask  = (const float*)d_in[4];
    const float* wq      = (const float*)d_in[5];
    const float* wk      = (const float*)d_in[6];
    const float* wv      = (const float*)d_in[7];
    const float* wo      = (const float*)d_in[8];
    float* out  = (float*)d_out;
    float* eout = out + (out_size - Bq);

    const int HG_SMEM = 2 * 40960;
    cudaFuncSetAttribute(hgemm_kernel, cudaFuncAttributeMaxDynamicSharedMemorySize, HG_SMEM);
    cudaFuncSetAttribute(attn4_kernel, cudaFuncAttributeMaxDynamicSharedMemorySize, ATTN4_SMEM);

    init_kernel<<<(Bq * Tn + 255) / 256, 256>>>();
    rowocc_kernel<<<(Bq * Qn) / 8, 256>>>(tmask, qtmask);
    colact_kernel<<<dim3(Tn / 256, Bq), 256>>>(tmask, qtmask);

    convA2_kernel<<<4096, 256>>>(qinput, 0);
    convA2_kernel<<<4096, 256>>>(kvinput, 1);
    convW2_kernel<<<dim3(16, 16, 3), 256>>>(wq, wk, wv);
    convWo2_kernel<<<dim3(16, 16), 256>>>(wo);

    for (int z = 0; z < 3; z++)
        hgemm_kernel<<<dim3(32, 8), 256, HG_SMEM>>>(0, nullptr, nullptr, z);

    convQK_kernel<<<4096, 256>>>(0);
    convQK_kernel<<<4096, 256>>>(1);
    convVT_kernel<<<dim3(16, 64), 256>>>();

    attn4_kernel<<<dim3(Qn / 128, Hn, Bq), 256, ATTN4_SMEM>>>(tmask, qtmask);

    colsum_kernel<<<dim3(Tn / 32, Hn, Bq), 256>>>(tmask, qtmask);
    entropy_kernel<<<Bq, 256>>>(eout);

    convA2_kernel<<<4096, 256>>>(nullptr, 2);
    hgemm_kernel<<<dim3(32, 8), 256, HG_SMEM>>>(1, qmask, out, 0);
}

// round 14
// speedup vs baseline: 2.4607x; 1.2059x over previous
#include <cuda_runtime.h>
#include <cuda_bf16.h>
#include <math.h>
#include <stdint.h>

#define Bq 4
#define Qn 1024
#define Tn 1024
#define Hn 16
#define Mn 1024
#define Kd 64
#define Vd 64

// ---------------- scratch (static device globals; no runtime alloc) ----------
__device__ float g_q[Bq*Hn*Qn*Kd];
__device__ float g_k[Bq*Hn*Tn*Kd];
__device__ float g_v[Bq*Hn*Tn*Vd];
__device__ float g_preF[Bq*Qn*Hn*Vd];  // [b*1024+q][h*64+d]
__device__ float g_m[Bq*Hn*Qn];
__device__ float g_l[Bq*Hn*Qn];
__device__ float g_rowocc[Bq*Qn];
__device__ float g_colact[Bq*Tn];
__device__ float g_colsum[Bq*Tn];

// bf16 hi/lo operands for GEMMs (row-major, k-contiguous)
__device__ __align__(16) __nv_bfloat16 cAq_h[4096*1024],  cAq_l[4096*1024];
__device__ __align__(16) __nv_bfloat16 cAkv_h[4096*1024], cAkv_l[4096*1024];
__device__ __align__(16) __nv_bfloat16 cApre_h[4096*1024],cApre_l[4096*1024];
__device__ __align__(16) __nv_bfloat16 cBq_h[1024*1024],  cBq_l[1024*1024];
__device__ __align__(16) __nv_bfloat16 cBk_h[1024*1024],  cBk_l[1024*1024];
__device__ __align__(16) __nv_bfloat16 cBv_h[1024*1024],  cBv_l[1024*1024];
__device__ __align__(16) __nv_bfloat16 cBo_h[1024*1024],  cBo_l[1024*1024];

// bf16 hi/lo for attention + colsum
__device__ __align__(16) __nv_bfloat16 g_qh[Bq*Hn*Qn*Kd], g_ql[Bq*Hn*Qn*Kd];
__device__ __align__(16) __nv_bfloat16 g_kh[Bq*Hn*Tn*Kd], g_kl[Bq*Hn*Tn*Kd];
__device__ __align__(16) __nv_bfloat16 g_vTh[Bq*Hn*Kd*Tn], g_vTl[Bq*Hn*Kd*Tn]; // [bh][d][t]

// ---------------- helpers ------------------------------------------------------
__device__ __forceinline__ uint32_t smem_u32(const void* p) {
    uint32_t a;
    asm("{ .reg .u64 t; cvta.to.shared.u64 t, %1; cvt.u32.u64 %0, t; }" : "=r"(a) : "l"(p));
    return a;
}
__device__ __forceinline__ void split2(float x, unsigned short &h, unsigned short &l) {
    __nv_bfloat16 hb = __float2bfloat16(x);
    float r = x - __bfloat162float(hb);
    __nv_bfloat16 lb = __float2bfloat16(r);
    h = __bfloat16_as_ushort(hb);
    l = __bfloat16_as_ushort(lb);
}
__device__ __forceinline__ float warpSum(float v) {
    #pragma unroll
    for (int o = 16; o > 0; o >>= 1) v += __shfl_xor_sync(0xffffffffu, v, o);
    return v;
}
#define LDX4(r0, r1, r2, r3, addr) \
    asm volatile("ldmatrix.sync.aligned.m8n8.x4.shared.b16 {%0,%1,%2,%3}, [%4];" \
        : "=r"(r0), "=r"(r1), "=r"(r2), "=r"(r3) : "r"(addr))
#define MMA16816(d, a, b) \
    asm volatile("mma.sync.aligned.m16n8k16.row.col.f32.bf16.bf16.f32 " \
        "{%0,%1,%2,%3}, {%4,%5,%6,%7}, {%8,%9}, {%0,%1,%2,%3};" \
        : "+f"((d)[0]), "+f"((d)[1]), "+f"((d)[2]), "+f"((d)[3]) \
        : "r"((a)[0]), "r"((a)[1]), "r"((a)[2]), "r"((a)[3]), "r"((b)[0]), "r"((b)[1]))

// ---------------- small kernels -------------------------------------------------
__global__ void init_kernel() {
    int i = blockIdx.x * blockDim.x + threadIdx.x;
    if (i < Bq * Tn) g_colsum[i] = 0.0f;
}

__global__ __launch_bounds__(256) void rowocc_kernel(const float* __restrict__ tmask,
                                                     const float* __restrict__ qtmask) {
    int warp = threadIdx.x >> 5, lane = threadIdx.x & 31;
    int row = blockIdx.x * 8 + warp;
    if (row >= Bq * Qn) return;
    int b = row / Qn;
    float acc = 0.0f;
    const float* qt = qtmask + (size_t)row * Tn;
    const float* tm = tmask + (size_t)b * Tn;
    for (int t = lane; t < Tn; t += 32)
        acc += 1.0f - fmaxf(tm[t], qt[t]);
    acc = warpSum(acc);
    if (lane == 0) g_rowocc[row] = acc;
}

__global__ __launch_bounds__(256) void colact_kernel(const float* __restrict__ tmask,
                                                     const float* __restrict__ qtmask) {
    int b = blockIdx.y;
    int t = blockIdx.x * blockDim.x + threadIdx.x;
    if (t >= Tn) return;
    float tmv = tmask[b * Tn + t];
    float mx = -1e30f;
    for (int q = 0; q < Qn; q++) {
        float occ = 1.0f - fmaxf(tmv, qtmask[((size_t)(b * Qn + q)) * Tn + t]);
        mx = fmaxf(mx, occ);
    }
    g_colact[b * Tn + t] = mx;
}

// ---------------- conversions ---------------------------------------------------
__global__ __launch_bounds__(256) void convA2_kernel(const float* __restrict__ srcp, int sel) {
    const float* src = srcp;
    __nv_bfloat16 *dh, *dl;
    if (sel == 0)      { dh = cAq_h;  dl = cAq_l;  }
    else if (sel == 1) { dh = cAkv_h; dl = cAkv_l; }
    else               { src = g_preF; dh = cApre_h; dl = cApre_l; }
    size_t i4 = ((size_t)blockIdx.x * 256 + threadIdx.x) * 4;
    float4 v = *(const float4*)&src[i4];
    unsigned short h0, l0, h1, l1, h2, l2, h3, l3;
    split2(v.x, h0, l0); split2(v.y, h1, l1); split2(v.z, h2, l2); split2(v.w, h3, l3);
    *(uint2*)&dh[i4] = make_uint2(((unsigned)h1 << 16) | h0, ((unsigned)h3 << 16) | h2);
    *(uint2*)&dl[i4] = make_uint2(((unsigned)l1 << 16) | l0, ((unsigned)l3 << 16) | l2);
}

__global__ __launch_bounds__(256) void convQK_kernel(int sel) {
    const float* src = sel ? g_k : g_q;
    __nv_bfloat16* dh = sel ? g_kh : g_qh;
    __nv_bfloat16* dl = sel ? g_kl : g_ql;
    size_t i4 = ((size_t)blockIdx.x * 256 + threadIdx.x) * 4;
    float4 v = *(const float4*)&src[i4];
    unsigned short h0, l0, h1, l1, h2, l2, h3, l3;
    split2(v.x, h0, l0); split2(v.y, h1, l1); split2(v.z, h2, l2); split2(v.w, h3, l3);
    *(uint2*)&dh[i4] = make_uint2(((unsigned)h1 << 16) | h0, ((unsigned)h3 << 16) | h2);
    *(uint2*)&dl[i4] = make_uint2(((unsigned)l1 << 16) | l0, ((unsigned)l3 << 16) | l2);
}

__global__ __launch_bounds__(256) void convVT_kernel() {
    __shared__ float st[64][65];
    int bh = blockIdx.y, t0 = blockIdx.x * 64;
    int tid = threadIdx.x;
    #pragma unroll
    for (int it = 0; it < 4; it++) {
        int e = (it * 256 + tid) * 4;
        int t = e >> 6, d = e & 63;
        float4 v = *(const float4*)&g_v[((size_t)bh * Tn + t0 + t) * 64 + d];
        st[t][d] = v.x; st[t][d + 1] = v.y; st[t][d + 2] = v.z; st[t][d + 3] = v.w;
    }
    __syncthreads();
    #pragma unroll
    for (int it = 0; it < 8; it++) {
        int u = it * 256 + tid;
        int d = u >> 5, tp = (u & 31) * 2;
        unsigned short h0, l0, h1, l1;
        split2(st[tp][d], h0, l0);
        split2(st[tp + 1][d], h1, l1);
        size_t idx = ((size_t)bh * 64 + d) * 1024 + t0 + tp;
        *(unsigned*)&g_vTh[idx] = ((unsigned)h1 << 16) | h0;
        *(unsigned*)&g_vTl[idx] = ((unsigned)l1 << 16) | l0;
    }
}

__global__ __launch_bounds__(256) void convW2_kernel(const float* __restrict__ wq_,
                                                     const float* __restrict__ wk_,
                                                     const float* __restrict__ wv_) {
    __shared__ float st[64][65];
    int z = blockIdx.z, h = blockIdx.x, mc = blockIdx.y;
    const float* W = (z == 0) ? wq_ : (z == 1) ? wk_ : wv_;
    __nv_bfloat16* dh = (z == 0) ? cBq_h : (z == 1) ? cBk_h : cBv_h;
    __nv_bfloat16* dl = (z == 0) ? cBq_l : (z == 1) ? cBk_l : cBv_l;
    float sc = (z == 0) ? 0.125f : 1.0f;
    int tid = threadIdx.x;
    #pragma unroll
    for (int i = 0; i < 4; i++) {
        int e = tid + i * 256;
        int mm = e >> 4, d4 = (e & 15) * 4;
        float4 v = *(const float4*)&W[(size_t)h * 65536 + (size_t)(mc * 64 + mm) * 64 + d4];
        st[mm][d4] = v.x * sc; st[mm][d4 + 1] = v.y * sc;
        st[mm][d4 + 2] = v.z * sc; st[mm][d4 + 3] = v.w * sc;
    }
    __syncthreads();
    int d = tid >> 2, mg = (tid & 3) * 16;
    unsigned ph[8], pl[8];
    #pragma unroll
    for (int j = 0; j < 8; j++) {
        unsigned short ha, la, hb, lb;
        split2(st[mg + 2 * j][d], ha, la);
        split2(st[mg + 2 * j + 1][d], hb, lb);
        ph[j] = ((unsigned)hb << 16) | ha;
        pl[j] = ((unsigned)lb << 16) | la;
    }
    size_t base = (size_t)(h * 64 + d) * 1024 + mc * 64 + mg;
    *(uint4*)&dh[base]     = make_uint4(ph[0], ph[1], ph[2], ph[3]);
    *(uint4*)&dh[base + 8] = make_uint4(ph[4], ph[5], ph[6], ph[7]);
    *(uint4*)&dl[base]     = make_uint4(pl[0], pl[1], pl[2], pl[3]);
    *(uint4*)&dl[base + 8] = make_uint4(pl[4], pl[5], pl[6], pl[7]);
}

__global__ __launch_bounds__(256) void convWo2_kernel(const float* __restrict__ wo) {
    __shared__ float st[64][65];
    int h = blockIdx.x, mc = blockIdx.y;
    int tid = threadIdx.x;
    #pragma unroll
    for (int i = 0; i < 4; i++) {
        int e = tid + i * 256;
        int v = e >> 4, m4 = (e & 15) * 4;
        float4 x = *(const float4*)&wo[(size_t)(h * 64 + v) * 1024 + mc * 64 + m4];
        st[v][m4] = x.x; st[v][m4 + 1] = x.y; st[v][m4 + 2] = x.z; st[v][m4 + 3] = x.w;
    }
    __syncthreads();
    int mm = tid >> 2, vg = (tid & 3) * 16;
    unsigned ph[8], pl[8];
    #pragma unroll
    for (int j = 0; j < 8; j++) {
        unsigned short ha, la, hb, lb;
        split2(st[vg + 2 * j][mm], ha, la);
        split2(st[vg + 2 * j + 1][mm], hb, lb);
        ph[j] = ((unsigned)hb << 16) | ha;
        pl[j] = ((unsigned)lb << 16) | la;
    }
    size_t base = (size_t)(mc * 64 + mm) * 1024 + h * 64 + vg;
    *(uint4*)&cBo_h[base]     = make_uint4(ph[0], ph[1], ph[2], ph[3]);
    *(uint4*)&cBo_h[base + 8] = make_uint4(ph[4], ph[5], ph[6], ph[7]);
    *(uint4*)&cBo_l[base]     = make_uint4(pl[0], pl[1], pl[2], pl[3]);
    *(uint4*)&cBo_l[base + 8] = make_uint4(pl[4], pl[5], pl[6], pl[7]);
}

// ---------------- HMMA GEMM (unchanged) -----------------------------------------
__device__ __forceinline__ void hg_prefetch(uint32_t sbuf,
        const __nv_bfloat16* Ah, const __nv_bfloat16* Al,
        const __nv_bfloat16* Bh, const __nv_bfloat16* Bl,
        int rowBase, int cn, int k0, int tid) {
    #pragma unroll
    for (int j = 0; j < 8; j++) {
        int lin = j * 256 + tid;
        int arr = lin >> 9, within = lin & 511;
        int row = within >> 2, seg = within & 3;
        const __nv_bfloat16* g;
        if (arr == 0)      g = Ah + (size_t)(rowBase + row) * 1024;
        else if (arr == 1) g = Al + (size_t)(rowBase + row) * 1024;
        else if (arr == 2) g = Bh + (size_t)(cn + row) * 1024;
        else               g = Bl + (size_t)(cn + row) * 1024;
        g += k0 + seg * 8;
        uint32_t s = sbuf + arr * 10240 + row * 80 + seg * 16;
        asm volatile("cp.async.cg.shared.global [%0], [%1], 16;" :: "r"(s), "l"(g));
    }
}

__global__ __launch_bounds__(256) void hgemm_kernel(int mode,
        const float* __restrict__ qmask, float* __restrict__ outp, int z) {
    extern __shared__ char sm[];
    uint32_t sb = smem_u32(sm);
    int tid = threadIdx.x, lane = tid & 31, wid = tid >> 5;
    int warp_m = wid & 1, warp_n = wid >> 1;

    const __nv_bfloat16 *Ah, *Al, *Bh, *Bl;
    float* C;
    if (mode == 0) {
        Ah = (z == 0) ? cAq_h : cAkv_h;
        Al = (z == 0) ? cAq_l : cAkv_l;
        Bh = (z == 0) ? cBq_h : (z == 1) ? cBk_h : cBv_h;
        Bl = (z == 0) ? cBq_l : (z == 1) ? cBk_l : cBv_l;
        C  = (z == 0) ? g_q : (z == 1) ? g_k : g_v;
    } else {
        Ah = cApre_h; Al = cApre_l; Bh = cBo_h; Bl = cBo_l; C = outp;
    }
    int rowBase = blockIdx.x * 128;
    int cn = blockIdx.y * 128;

    float acc[4][4][4];
    #pragma unroll
    for (int i = 0; i < 4; i++)
        #pragma unroll
        for (int j = 0; j < 4; j++)
            #pragma unroll
            for (int r = 0; r < 4; r++) acc[i][j][r] = 0.0f;

    int laneRow = lane & 15, laneK = lane >> 4;
    uint32_t aOff = (uint32_t)((warp_m * 64 + laneRow) * 80 + laneK * 16);
    uint32_t bOff = (uint32_t)(20480 + (warp_n * 32 + laneRow) * 80 + laneK * 16);

    hg_prefetch(sb, Ah, Al, Bh, Bl, rowBase, cn, 0, tid);
    asm volatile("cp.async.commit_group;");

    for (int c = 0; c < 32; c++) {
        uint32_t sbuf = sb + (c & 1) * 40960;
        if (c < 31) {
            hg_prefetch(sb + ((c + 1) & 1) * 40960, Ah, Al, Bh, Bl, rowBase, cn, (c + 1) * 32, tid);
            asm volatile("cp.async.commit_group;");
            asm volatile("cp.async.wait_group 1;");
        } else {
            asm volatile("cp.async.wait_group 0;");
        }
        __syncthreads();

        #pragma unroll
        for (int ks = 0; ks < 2; ks++) {
            uint32_t kOff = ks * 32;
            unsigned bh[4][2], bl[4][2];
            {
                unsigned r0, r1, r2, r3;
                LDX4(r0, r1, r2, r3, sbuf + bOff + kOff);
                bh[0][0] = r0; bh[0][1] = r2; bh[1][0] = r1; bh[1][1] = r3;
                LDX4(r0, r1, r2, r3, sbuf + bOff + kOff + 1280);
                bh[2][0] = r0; bh[2][1] = r2; bh[3][0] = r1; bh[3][1] = r3;
                LDX4(r0, r1, r2, r3, sbuf + bOff + kOff + 10240);
                bl[0][0] = r0; bl[0][1] = r2; bl[1][0] = r1; bl[1][1] = r3;
                LDX4(r0, r1, r2, r3, sbuf + bOff + kOff + 11520);
                bl[2][0] = r0; bl[2][1] = r2; bl[3][0] = r1; bl[3][1] = r3;
            }
            #pragma unroll
            for (int mt = 0; mt < 4; mt++) {
                unsigned ah[4], al4[4];
                uint32_t aAddr = sbuf + aOff + kOff + mt * 1280;
                LDX4(ah[0], ah[1], ah[2], ah[3], aAddr);
                LDX4(al4[0], al4[1], al4[2], al4[3], aAddr + 10240);
                #pragma unroll
                for (int nt = 0; nt < 4; nt++) {
                    MMA16816(acc[mt][nt], ah, bh[nt]);
                    MMA16816(acc[mt][nt], ah, bl[nt]);
                    MMA16816(acc[mt][nt], al4, bh[nt]);
                }
            }
        }
        __syncthreads();
    }

    int g = lane >> 2, tc = (lane & 3) * 2;
    #pragma unroll
    for (int mt = 0; mt < 4; mt++) {
        #pragma unroll
        for (int nt = 0; nt < 4; nt++) {
            int r0 = rowBase + warp_m * 64 + mt * 16 + g;
            int cc = cn + warp_n * 32 + nt * 8 + tc;
            if (mode == 0) {
                int h = cc >> 6, d = cc & 63;
                int b0 = r0 >> 10, q0 = r0 & 1023;
                float* d0 = &C[(((size_t)(b0 * Hn + h)) * Qn + q0) * Kd + d];
                *(float2*)d0 = make_float2(acc[mt][nt][0], acc[mt][nt][1]);
                int r1 = r0 + 8;
                int b1 = r1 >> 10, q1 = r1 & 1023;
                float* d1 = &C[(((size_t)(b1 * Hn + h)) * Qn + q1) * Kd + d];
                *(float2*)d1 = make_float2(acc[mt][nt][2], acc[mt][nt][3]);
            } else {
                float w0 = 1.0f - qmask[r0];
                float w1 = 1.0f - qmask[r0 + 8];
                *(float2*)&C[(size_t)r0 * 1024 + cc] =
                    make_float2(acc[mt][nt][0] * w0, acc[mt][nt][1] * w0);
                *(float2*)&C[(size_t)(r0 + 8) * 1024 + cc] =
                    make_float2(acc[mt][nt][2] * w1, acc[mt][nt][3] * w1);
            }
        }
    }
}

// ---------------- flash attention via HMMA (R12, unchanged) ---------------------
#define QH_OFF 0
#define QL_OFF 18432
#define KH_OFF 36864
#define KL_OFF 46080
#define VTH_OFF 55296
#define VTL_OFF 64512
#define ATTN4_SMEM 73728

__global__ __launch_bounds__(256) void attn4_kernel(const float* __restrict__ tmask,
                                                    const float* __restrict__ qtmask) {
    extern __shared__ char sm4[];
    uint32_t sb = smem_u32(sm4);
    int b = blockIdx.z, h = blockIdx.y;
    int qb = (gridDim.x - 1 - blockIdx.x) * 128;
    int bh = b * Hn + h;
    int tid = threadIdx.x, lane = tid & 31, w = tid >> 5;
    int laneRow = lane & 15, laneK = lane >> 4;
    int g = lane >> 2, qc = lane & 3;

    #pragma unroll
    for (int j = 0; j < 8; j++) {
        int lin = j * 256 + tid;
        int arr = lin >> 10, row = (lin >> 3) & 127, seg = lin & 7;
        const __nv_bfloat16* src = (arr ? g_ql : g_qh) + ((size_t)bh * Qn + qb + row) * 64 + seg * 8;
        uint32_t dst = sb + (arr ? QL_OFF : QH_OFF) + row * 144 + seg * 16;
        asm volatile("cp.async.cg.shared.global [%0], [%1], 16;" :: "r"(dst), "l"(src));
    }
    asm volatile("cp.async.commit_group;");

    float accO[8][4];
    #pragma unroll
    for (int i = 0; i < 8; i++)
        #pragma unroll
        for (int r = 0; r < 4; r++) accO[i][r] = 0.0f;
    float mrow[2] = {-1e30f, -1e30f}, lrow[2] = {0.0f, 0.0f};

    int qmin = qb + 16 * w, qmax = qmin + 15;
    int ntls = qb / 64 + 2;

    for (int tile = 0; tile < ntls; tile++) {
        int t0 = tile * 64;
        __syncthreads();
        #pragma unroll
        for (int j = 0; j < 8; j++) {
            int lin = j * 256 + tid;
            int arr = lin >> 9, within = lin & 511;
            int row = within >> 3, seg = within & 7;
            const __nv_bfloat16* src;
            uint32_t off;
            if (arr == 0)      { src = g_kh + ((size_t)bh * Tn + t0 + row) * 64 + seg * 8; off = KH_OFF; }
            else if (arr == 1) { src = g_kl + ((size_t)bh * Tn + t0 + row) * 64 + seg * 8; off = KL_OFF; }
            else if (arr == 2) { src = g_vTh + ((size_t)bh * 64 + row) * 1024 + t0 + seg * 8; off = VTH_OFF; }
            else               { src = g_vTl + ((size_t)bh * 64 + row) * 1024 + t0 + seg * 8; off = VTL_OFF; }
            uint32_t dst = sb + off + row * 144 + seg * 16;
            asm volatile("cp.async.cg.shared.global [%0], [%1], 16;" :: "r"(dst), "l"(src));
        }
        asm volatile("cp.async.commit_group;");
        asm volatile("cp.async.wait_group 0;");
        __syncthreads();

        if (t0 > qmax) continue;

        float accS[8][4];
        #pragma unroll
        for (int i = 0; i < 8; i++)
            #pragma unroll
            for (int r = 0; r < 4; r++) accS[i][r] = 0.0f;

        #pragma unroll
        for (int ks = 0; ks < 4; ks++) {
            uint32_t kOff = ks * 32;
            unsigned ah[4], al[4];
            uint32_t aAddr = sb + (16 * w + laneRow) * 144 + kOff + laneK * 16;
            LDX4(ah[0], ah[1], ah[2], ah[3], aAddr + QH_OFF);
            LDX4(al[0], al[1], al[2], al[3], aAddr + QL_OFF);
            unsigned kh2[8][2], kl2[8][2];
            #pragma unroll
            for (int p = 0; p < 4; p++) {
                unsigned r0, r1, r2, r3;
                uint32_t bAddr = sb + (p * 16 + laneRow) * 144 + kOff + laneK * 16;
                LDX4(r0, r1, r2, r3, bAddr + KH_OFF);
                kh2[2*p][0] = r0; kh2[2*p+1][0] = r1; kh2[2*p][1] = r2; kh2[2*p+1][1] = r3;
                LDX4(r0, r1, r2, r3, bAddr + KL_OFF);
                kl2[2*p][0] = r0; kl2[2*p+1][0] = r1; kl2[2*p][1] = r2; kl2[2*p+1][1] = r3;
            }
            #pragma unroll
            for (int nt = 0; nt < 8; nt++) {
                MMA16816(accS[nt], ah, kh2[nt]);
                MMA16816(accS[nt], ah, kl2[nt]);
                MMA16816(accS[nt], al, kh2[nt]);
            }
        }

        bool full = (t0 + 63 <= qmin);
        if (!full) {
            float tmv[8][2];
            #pragma unroll
            for (int nt = 0; nt < 8; nt++) {
                tmv[nt][0] = tmask[b * Tn + t0 + nt * 8 + qc * 2];
                tmv[nt][1] = tmask[b * Tn + t0 + nt * 8 + qc * 2 + 1];
            }
            #pragma unroll
            for (int rr = 0; rr < 2; rr++) {
                int q = qmin + g + rr * 8;
                const float* qtrow = qtmask + ((size_t)(b * Qn + q)) * Tn;
                #pragma unroll
                for (int nt = 0; nt < 8; nt++) {
                    #pragma unroll
                    for (int c = 0; c < 2; c++) {
                        int t = t0 + nt * 8 + qc * 2 + c;
                        if (!((1.0f - fmaxf(tmv[nt][c], qtrow[t])) > 0.0f))
                            accS[nt][rr * 2 + c] = -1e30f;
                    }
                }
            }
        }

        #pragma unroll
        for (int rr = 0; rr < 2; rr++) {
            float rmax = -1e30f;
            #pragma unroll
            for (int nt = 0; nt < 8; nt++)
                rmax = fmaxf(rmax, fmaxf(accS[nt][rr * 2], accS[nt][rr * 2 + 1]));
            rmax = fmaxf(rmax, __shfl_xor_sync(0xffffffffu, rmax, 1));
            rmax = fmaxf(rmax, __shfl_xor_sync(0xffffffffu, rmax, 2));
            float mnew = fmaxf(mrow[rr], rmax);
            float sc = __expf(mrow[rr] - mnew);
            float ps = 0.0f;
            #pragma unroll
            for (int nt = 0; nt < 8; nt++) {
                float p0 = __expf(accS[nt][rr * 2] - mnew);
                float p1 = __expf(accS[nt][rr * 2 + 1] - mnew);
                accS[nt][rr * 2] = p0; accS[nt][rr * 2 + 1] = p1;
                ps += p0 + p1;
            }
            ps += __shfl_xor_sync(0xffffffffu, ps, 1);
            ps += __shfl_xor_sync(0xffffffffu, ps, 2);
            lrow[rr] = lrow[rr] * sc + ps;
            mrow[rr] = mnew;
            #pragma unroll
            for (int dt = 0; dt < 8; dt++) {
                accO[dt][rr * 2] *= sc;
                accO[dt][rr * 2 + 1] *= sc;
            }
        }

        #pragma unroll
        for (int kt = 0; kt < 4; kt++) {
            unsigned pah[4], pal[4];
            #pragma unroll
            for (int fi = 0; fi < 4; fi++) {
                int nt = 2 * kt + (fi >> 1);
                int base = (fi & 1) * 2;
                unsigned short ha, la, hb2, lb2;
                split2(accS[nt][base], ha, la);
                split2(accS[nt][base + 1], hb2, lb2);
                pah[fi] = ((unsigned)hb2 << 16) | ha;
                pal[fi] = ((unsigned)lb2 << 16) | la;
            }
            unsigned vh2[8][2], vl2[8][2];
            #pragma unroll
            for (int p = 0; p < 4; p++) {
                unsigned r0, r1, r2, r3;
                uint32_t bAddr = sb + (p * 16 + laneRow) * 144 + kt * 32 + laneK * 16;
                LDX4(r0, r1, r2, r3, bAddr + VTH_OFF);
                vh2[2*p][0] = r0; vh2[2*p+1][0] = r1; vh2[2*p][1] = r2; vh2[2*p+1][1] = r3;
                LDX4(r0, r1, r2, r3, bAddr + VTL_OFF);
                vl2[2*p][0] = r0; vl2[2*p+1][0] = r1; vl2[2*p][1] = r2; vl2[2*p+1][1] = r3;
            }
            #pragma unroll
            for (int dt = 0; dt < 8; dt++) {
                MMA16816(accO[dt], pah, vh2[dt]);
                MMA16816(accO[dt], pah, vl2[dt]);
                MMA16816(accO[dt], pal, vh2[dt]);
            }
        }
    }

    #pragma unroll
    for (int rr = 0; rr < 2; rr++) {
        int q = qmin + g + rr * 8;
        float inv = 1.0f / lrow[rr];
        #pragma unroll
        for (int dt = 0; dt < 8; dt++) {
            int d = dt * 8 + qc * 2;
            *(float2*)&g_preF[((size_t)(b * Qn + q)) * 1024 + h * 64 + d] =
                make_float2(accO[dt][rr * 2] * inv, accO[dt][rr * 2 + 1] * inv);
        }
        if (qc == 0) {
            g_m[bh * Qn + q] = mrow[rr];
            g_l[bh * Qn + q] = lrow[rr];
        }
    }
}

// ---------------- column sums via HMMA ------------------------------------------
// block: 128 t-rows; A = K tile (cached in regs), B = Q 64-chunks streamed.
#define CK_KH 0
#define CK_KL 18432
#define CK_QH 36864
#define CK_QL 46080
#define CK_MS 55296
#define CK_WS 55552
#define COLSUM_SMEM 55808

__global__ __launch_bounds__(256) void colsum2_kernel(const float* __restrict__ tmask,
                                                      const float* __restrict__ qtmask) {
    extern __shared__ char smc[];
    uint32_t sb = smem_u32(smc);
    float* msp = (float*)(smc + CK_MS);
    float* wsp = (float*)(smc + CK_WS);
    int b = blockIdx.z, h = blockIdx.y;
    int tb = blockIdx.x * 128;
    int bh = b * Hn + h;
    int tid = threadIdx.x, lane = tid & 31, w = tid >> 5;
    int laneRow = lane & 15, laneK = lane >> 4;
    int g = lane >> 2, qc = lane & 3;

    // load K tile (128 t x 64 d, hi/lo)
    #pragma unroll
    for (int j = 0; j < 8; j++) {
        int lin = j * 256 + tid;
        int arr = lin >> 10, within = lin & 1023;
        int row = within >> 3, seg = within & 7;
        const __nv_bfloat16* src = (arr ? g_kl : g_kh) + ((size_t)bh * Tn + tb + row) * 64 + seg * 8;
        uint32_t dst = sb + (arr ? CK_KL : CK_KH) + row * 144 + seg * 16;
        asm volatile("cp.async.cg.shared.global [%0], [%1], 16;" :: "r"(dst), "l"(src));
    }
    asm volatile("cp.async.commit_group;");
    asm volatile("cp.async.wait_group 0;");
    __syncthreads();

    // cache K A-fragments (invariant across q tiles)
    unsigned kfh[4][4], kfl[4][4];
    #pragma unroll
    for (int ks = 0; ks < 4; ks++) {
        uint32_t aAddr = sb + (16 * w + laneRow) * 144 + ks * 32 + laneK * 16;
        LDX4(kfh[ks][0], kfh[ks][1], kfh[ks][2], kfh[ks][3], aAddr + CK_KH);
        LDX4(kfl[ks][0], kfl[ks][1], kfl[ks][2], kfl[ks][3], aAddr + CK_KL);
    }

    float colacc[2] = {0.0f, 0.0f};
    int t_r0 = tb + 16 * w + g, t_r1 = t_r0 + 8;

    for (int q0 = tb; q0 < Qn; q0 += 64) {
        __syncthreads();   // previous tile's Q reads done
        #pragma unroll
        for (int j = 0; j < 4; j++) {
            int lin = j * 256 + tid;
            int arr = lin >> 9, within = lin & 511;
            int row = within >> 3, seg = within & 7;
            const __nv_bfloat16* src = (arr ? g_ql : g_qh) + ((size_t)bh * Qn + q0 + row) * 64 + seg * 8;
            uint32_t dst = sb + (arr ? CK_QL : CK_QH) + row * 144 + seg * 16;
            asm volatile("cp.async.cg.shared.global [%0], [%1], 16;" :: "r"(dst), "l"(src));
        }
        asm volatile("cp.async.commit_group;");
        if (tid < 64) {
            msp[tid] = g_m[bh * Qn + q0 + tid];
            wsp[tid] = g_rowocc[b * Qn + q0 + tid] / g_l[bh * Qn + q0 + tid];
        }
        asm volatile("cp.async.wait_group 0;");
        __syncthreads();

        float accS[8][4];
        #pragma unroll
        for (int i = 0; i < 8; i++)
            #pragma unroll
            for (int r = 0; r < 4; r++) accS[i][r] = 0.0f;

        #pragma unroll
        for (int ks = 0; ks < 4; ks++) {
            unsigned qh2[8][2], ql2[8][2];
            #pragma unroll
            for (int p = 0; p < 4; p++) {
                unsigned r0, r1, r2, r3;
                uint32_t bAddr = sb + (p * 16 + laneRow) * 144 + ks * 32 + laneK * 16;
                LDX4(r0, r1, r2, r3, bAddr + CK_QH);
                qh2[2*p][0] = r0; qh2[2*p+1][0] = r1; qh2[2*p][1] = r2; qh2[2*p+1][1] = r3;
                LDX4(r0, r1, r2, r3, bAddr + CK_QL);
                ql2[2*p][0] = r0; ql2[2*p+1][0] = r1; ql2[2*p][1] = r2; ql2[2*p+1][1] = r3;
            }
            #pragma unroll
            for (int nt = 0; nt < 8; nt++) {
                MMA16816(accS[nt], kfh[ks], qh2[nt]);
                MMA16816(accS[nt], kfh[ks], ql2[nt]);
                MMA16816(accS[nt], kfl[ks], qh2[nt]);
            }
        }

        bool partial = (q0 - tb) < 128;
        if (partial) {
            float tmv0 = tmask[b * Tn + t_r0];
            float tmv1 = tmask[b * Tn + t_r1];
            #pragma unroll
            for (int nt = 0; nt < 8; nt++) {
                #pragma unroll
                for (int c = 0; c < 2; c++) {
                    int qi = nt * 8 + qc * 2 + c;
                    int q = q0 + qi;
                    float e0 = __expf(accS[nt][c] - msp[qi]) * wsp[qi];
                    float e1 = __expf(accS[nt][2 + c] - msp[qi]) * wsp[qi];
                    const float* qtrow = qtmask + ((size_t)(b * Qn + q)) * Tn;
                    bool a0 = (1.0f - fmaxf(tmv0, qtrow[t_r0])) > 0.0f;
                    bool a1 = (1.0f - fmaxf(tmv1, qtrow[t_r1])) > 0.0f;
                    colacc[0] += a0 ? e0 : 0.0f;
                    colacc[1] += a1 ? e1 : 0.0f;
                }
            }
        } else {
            #pragma unroll
            for (int nt = 0; nt < 8; nt++) {
                #pragma unroll
                for (int c = 0; c < 2; c++) {
                    int qi = nt * 8 + qc * 2 + c;
                    float mq = msp[qi], wq = wsp[qi];
                    colacc[0] += __expf(accS[nt][c] - mq) * wq;
                    colacc[1] += __expf(accS[nt][2 + c] - mq) * wq;
                }
            }
        }
    }

    #pragma unroll
    for (int rr = 0; rr < 2; rr++) {
        float v = colacc[rr];
        v += __shfl_xor_sync(0xffffffffu, v, 1);
        v += __shfl_xor_sync(0xffffffffu, v, 2);
        if (qc == 0)
            atomicAdd(&g_colsum[b * Tn + (rr ? t_r1 : t_r0)], v);
    }
}

// ---------------- entropy -------------------------------------------------------
__global__ __launch_bounds__(256) void entropy_kernel(float* __restrict__ eout) {
    int b = blockIdx.x, tid = threadIdx.x;
    int lane = tid & 31, warp = tid >> 5;
    __shared__ float sh0[8], sh1[8];
    float sm = 0.0f, sa = 0.0f;
    for (int t = tid; t < Tn; t += 256) {
        sm += g_colsum[b * Tn + t];
        sa += g_colact[b * Tn + t];
    }
    sm = warpSum(sm); sa = warpSum(sa);
    if (lane == 0) { sh0[warp] = sm; sh1[warp] = sa; }
    __syncthreads();
    float tsum = 0.0f, csum = 0.0f;
    #pragma unroll
    for (int w = 0; w < 8; w++) { tsum += sh0[w]; csum += sh1[w]; }
    __syncthreads();
    float ent = 0.0f;
    for (int t = tid; t < Tn; t += 256) {
        float p = g_colsum[b * Tn + t] / tsum;
        if (g_colact[b * Tn + t] > 0.0f && p > 0.0f) ent -= p * log2f(p);
    }
    ent = warpSum(ent);
    if (lane == 0) sh0[warp] = ent;
    __syncthreads();
    if (tid == 0) {
        float e = 0.0f;
        #pragma unroll
        for (int w = 0; w < 8; w++) e += sh0[w];
        eout[b] = e / log2f(csum);
    }
}

// ---------------- launch --------------------------------------------------------
extern "C" void kernel_launch(void* const* d_in, const int* in_sizes, int n_in,
                              void* d_out, int out_size) {
    const float* qinput  = (const float*)d_in[0];
    const float* kvinput = (const float*)d_in[1];
    const float* qmask   = (const float*)d_in[2];
    const float* tmask   = (const float*)d_in[3];
    const float* qtmask  = (const float*)d_in[4];
    const float* wq      = (const float*)d_in[5];
    const float* wk      = (const float*)d_in[6];
    const float* wv      = (const float*)d_in[7];
    const float* wo      = (const float*)d_in[8];
    float* out  = (float*)d_out;
    float* eout = out + (out_size - Bq);

    const int HG_SMEM = 2 * 40960;
    cudaFuncSetAttribute(hgemm_kernel, cudaFuncAttributeMaxDynamicSharedMemorySize, HG_SMEM);
    cudaFuncSetAttribute(attn4_kernel, cudaFuncAttributeMaxDynamicSharedMemorySize, ATTN4_SMEM);
    cudaFuncSetAttribute(colsum2_kernel, cudaFuncAttributeMaxDynamicSharedMemorySize, COLSUM_SMEM);

    init_kernel<<<(Bq * Tn + 255) / 256, 256>>>();
    rowocc_kernel<<<(Bq * Qn) / 8, 256>>>(tmask, qtmask);
    colact_kernel<<<dim3(Tn / 256, Bq), 256>>>(tmask, qtmask);

    convA2_kernel<<<4096, 256>>>(qinput, 0);
    convA2_kernel<<<4096, 256>>>(kvinput, 1);
    convW2_kernel<<<dim3(16, 16, 3), 256>>>(wq, wk, wv);
    convWo2_kernel<<<dim3(16, 16), 256>>>(wo);

    for (int z = 0; z < 3; z++)
        hgemm_kernel<<<dim3(32, 8), 256, HG_SMEM>>>(0, nullptr, nullptr, z);

    convQK_kernel<<<4096, 256>>>(0);
    convQK_kernel<<<4096, 256>>>(1);
    convVT_kernel<<<dim3(16, 64), 256>>>();

    attn4_kernel<<<dim3(Qn / 128, Hn, Bq), 256, ATTN4_SMEM>>>(tmask, qtmask);

    colsum2_kernel<<<dim3(Tn / 128, Hn, Bq), 256, COLSUM_SMEM>>>(tmask, qtmask);
    entropy_kernel<<<Bq, 256>>>(eout);

    convA2_kernel<<<4096, 256>>>(nullptr, 2);
    hgemm_kernel<<<dim3(32, 8), 256, HG_SMEM>>>(1, qmask, out, 0);
}